// round 12
// baseline (speedup 1.0000x reference)
#include <cuda_runtime.h>
#include <math.h>

#define BB 4
#define HH 192
#define WW 192
#define CC 64
#define HO 186
#define BHW (BB*HH*WW)          /* 147456 */

// padded x-conv scratch: per (array,batch) plane, rows [0,8) and [200,216) are zero
#define HP   216
#define PADT 8
#define XSTR ((size_t)HP*WW*CC)   /* 2654208 floats per plane */

// ---------------- scratch (device globals; no allocs allowed) ----------------
__device__ __align__(256) float g_X[6*BB*HP*WW*CC]; // plane(a,b)=a*BB+b
__device__ float  g_P0[10*BHW];    // sigma0: [e][b*H*W] full channel sums
__device__ float  g_P1[10*2*BHW];  // sigma1: [e*2+chalf][b*H*W] half sums
__device__ float2 g_fxe[2][7];     // x-factors folded: (ord0, ord2) taps 0..R
__device__ float  g_fxo[2][6];     // x-factor order1 taps 0..R-1 (antisym)
__device__ float4 g_fe[2][7];      // y-factors even maps: (L0, L3, L2, L5)
__device__ float2 g_fo[2][6];      // y-factors odd  maps: (L1, L4)
__device__ float  g_wy[7];         // integrator y factor
__device__ float  g_wx[7];         // integrator x factor

// -------- zero the pad rows of all 24 planes (graph-safe, deterministic) -----
__global__ void __launch_bounds__(256) zero_pads() {
    const int blk = blockIdx.x;            // 24 planes * 24 pad rows = 576
    const int p = blk / 24, r = blk % 24;
    const int row = (r < PADT) ? r : (HH + r);   // rows 0..7 and 200..215
    float4* dst = (float4*)&g_X[(size_t)p*XSTR + (size_t)row*WW*CC];
    const float4 Z = make_float4(0.f,0.f,0.f,0.f);
    for (int i = threadIdx.x; i < WW*CC/4; i += 256) dst[i] = Z;
}

// -------- factorization: parallel load to smem, warp argmax, tiny serial tail
__global__ void __launch_bounds__(256) factorize(const float* __restrict__ k0,
                                                 const float* __restrict__ k1,
                                                 const float* __restrict__ dgi) {
    __shared__ float sk[294 + 1014 + 49];
    __shared__ int   s_r0[7], s_c0[7];
    __shared__ float s_piv[7];
    float* sk0 = sk;
    float* sk1 = sk + 294;
    float* sdg = sk + 294 + 1014;
    const int tid = threadIdx.x;
    for (int i = tid; i < 294;  i += 256) sk0[i] = k0[(size_t)i*CC];
    for (int i = tid; i < 1014; i += 256) sk1[i] = k1[(size_t)i*CC];
    for (int i = tid; i < 49;   i += 256) sdg[i] = dgi[(size_t)i*CC];
    __syncthreads();

    const int warp = tid >> 5, lane = tid & 31;
    const int canon[3] = {0, 2, 5};
    if (warp < 7) {
        const float* base; int Ksz, n;
        if (warp < 3)      { base = sk0 + canon[warp]*49;        Ksz = 7;  n = 49;  }
        else if (warp < 6) { base = sk1 + canon[warp - 3]*169;   Ksz = 13; n = 169; }
        else               { base = sdg;                          Ksz = 7;  n = 49;  }
        float best = -1.f; int bidx = 0;
        for (int i = lane; i < n; i += 32) {
            float v = fabsf(base[i]);
            if (v > best) { best = v; bidx = i; }
        }
        #pragma unroll
        for (int off = 16; off >= 1; off >>= 1) {
            float ob = __shfl_xor_sync(0xffffffffu, best, off);
            int   oi = __shfl_xor_sync(0xffffffffu, bidx, off);
            if (ob > best || (ob == best && oi < bidx)) { best = ob; bidx = oi; }
        }
        if (lane == 0) {
            s_r0[warp] = bidx / Ksz; s_c0[warp] = bidx % Ksz; s_piv[warp] = base[bidx];
        }
    }
    __syncthreads();

    if (tid != 0) return;
    const int kxo[6]  = {0, 0, 1, 0, 1, 2};
    const float comb[6] = {1.f, 1.f, 1.f, 1.f, 1.41421356237309515f, 1.f};
    for (int s = 0; s < 2; ++s) {
        const float* skb = s ? sk1 : sk0;
        const int Ksz = s ? 13 : 7, R = (Ksz - 1)/2, per = Ksz*Ksz;
        float fx[3][13]; int c0s[3];
        for (int o = 0; o < 3; ++o) {
            const int task = s*3 + o;
            const int r0 = s_r0[task]; c0s[o] = s_c0[task];
            const float piv = s_piv[task];
            const float* Km = skb + canon[o]*per;
            for (int j = 0; j < Ksz; ++j) fx[o][j] = Km[r0*Ksz + j] / piv;
        }
        for (int t = 0; t <= R; ++t) g_fxe[s][t] = make_float2(fx[0][t], fx[2][t]);
        for (int t = 0; t <  R; ++t) g_fxo[s][t] = fx[1][t];
        float fy[6][13];
        for (int m = 0; m < 6; ++m) {
            const int c0 = c0s[kxo[m]];
            for (int i = 0; i < Ksz; ++i) fy[m][i] = skb[m*per + i*Ksz + c0] * comb[m];
        }
        for (int t = 0; t <= R; ++t)
            g_fe[s][t] = make_float4(fy[0][t], fy[3][t], fy[2][t], fy[5][t]);
        for (int t = 0; t <  R; ++t)
            g_fo[s][t] = make_float2(fy[1][t], fy[4][t]);
    }
    {
        const int r0 = s_r0[6], c0 = s_c0[6]; const float piv = s_piv[6];
        for (int i = 0; i < 7; ++i) g_wy[i] = sdg[i*7 + c0];
        for (int j = 0; j < 7; ++j) g_wx[j] = sdg[r0*7 + j] / piv;
    }
}

// ------- stage 1 (merged): x-convs for BOTH sigmas, orders 0..2 each --------
__global__ void __launch_bounds__(256) stage1_both(const float* __restrict__ in) {
    constexpr int XT = 64;
    __shared__ float2 s_in[(XT + 12)*32];
    const int b = blockIdx.z, yrow = blockIdx.y, x0 = blockIdx.x*XT;
    const int tid = threadIdx.x;
    const float2* rowv = (const float2*)(in + ((size_t)(b*HH + yrow)*WW)*CC);
    for (int t = tid; t < (XT + 12)*32; t += 256) {
        int xx = (t >> 5) - 6 + x0;
        int c2 = t & 31;
        s_in[t] = (xx >= 0 && xx < WW) ? rowv[xx*32 + c2] : make_float2(0.f, 0.f);
    }
    float2 fxe0[4], fxe1[7]; float fxo0[3], fxo1[6];
    #pragma unroll
    for (int t = 0; t < 4; ++t) fxe0[t] = g_fxe[0][t];
    #pragma unroll
    for (int t = 0; t < 3; ++t) fxo0[t] = g_fxo[0][t];
    #pragma unroll
    for (int t = 0; t < 7; ++t) fxe1[t] = g_fxe[1][t];
    #pragma unroll
    for (int t = 0; t < 6; ++t) fxo1[t] = g_fxo[1][t];
    __syncthreads();

    const int c2 = tid & 31, xg = tid >> 5;
    const size_t rowoff = (size_t)(yrow + PADT)*WW*CC;
    float2* o00 = (float2*)&g_X[(size_t)(0*BB + b)*XSTR + rowoff];
    float2* o01 = (float2*)&g_X[(size_t)(1*BB + b)*XSTR + rowoff];
    float2* o02 = (float2*)&g_X[(size_t)(2*BB + b)*XSTR + rowoff];
    float2* o10 = (float2*)&g_X[(size_t)(3*BB + b)*XSTR + rowoff];
    float2* o11 = (float2*)&g_X[(size_t)(4*BB + b)*XSTR + rowoff];
    float2* o12 = (float2*)&g_X[(size_t)(5*BB + b)*XSTR + rowoff];
    #pragma unroll
    for (int xq = 0; xq < 8; ++xq) {
        int xi = xg*8 + xq;
        float2 A0={0.f,0.f}, A1={0.f,0.f}, A2={0.f,0.f};
        float2 B0={0.f,0.f}, B1={0.f,0.f}, B2={0.f,0.f};
        #pragma unroll
        for (int t = 0; t < 6; ++t) {
            float2 u = s_in[(xi + t)*32 + c2];
            float2 v = s_in[(xi + 12 - t)*32 + c2];
            float sx = u.x + v.x, sy = u.y + v.y;
            float dx = u.x - v.x, dy = u.y - v.y;
            B0.x = fmaf(fxe1[t].x, sx, B0.x); B0.y = fmaf(fxe1[t].x, sy, B0.y);
            B2.x = fmaf(fxe1[t].y, sx, B2.x); B2.y = fmaf(fxe1[t].y, sy, B2.y);
            B1.x = fmaf(fxo1[t],   dx, B1.x); B1.y = fmaf(fxo1[t],   dy, B1.y);
            if (t >= 3) {
                const int t0 = t - 3;
                A0.x = fmaf(fxe0[t0].x, sx, A0.x); A0.y = fmaf(fxe0[t0].x, sy, A0.y);
                A2.x = fmaf(fxe0[t0].y, sx, A2.x); A2.y = fmaf(fxe0[t0].y, sy, A2.y);
                A1.x = fmaf(fxo0[t0],   dx, A1.x); A1.y = fmaf(fxo0[t0],   dy, A1.y);
            }
        }
        float2 m = s_in[(xi + 6)*32 + c2];
        B0.x = fmaf(fxe1[6].x, m.x, B0.x); B0.y = fmaf(fxe1[6].x, m.y, B0.y);
        B2.x = fmaf(fxe1[6].y, m.x, B2.x); B2.y = fmaf(fxe1[6].y, m.y, B2.y);
        A0.x = fmaf(fxe0[3].x, m.x, A0.x); A0.y = fmaf(fxe0[3].x, m.y, A0.y);
        A2.x = fmaf(fxe0[3].y, m.x, A2.x); A2.y = fmaf(fxe0[3].y, m.y, A2.y);
        int off = (x0 + xi)*32 + c2;
        o00[off] = A0; o01[off] = A1; o02[off] = A2;
        o10[off] = B0; o11[off] = B1; o12[off] = B2;
    }
}

// ---- reduction routing shared by both stage2 variants -----------------------
#define REDUCE_ROUTING() \
    const bool h4 = (lane & 16) != 0; \
    const bool h3 = (lane & 8)  != 0; \
    const bool h2 = (lane & 4)  != 0; \
    const bool h1 = (lane & 2)  != 0; \
    const bool two = (!h3) && (!h2); \
    const int  m4 = lane & 15; \
    const int  f  = (m4==0) ? 0 : (m4==2) ? 1 : (m4==4) ? 2 : (m4==8) ? 3 : 4; \
    const int  eidx = (h4 ? 5 : 0) + f; \
    const bool writer = (m4==0 || m4==2 || m4==4 || m4==8 || m4==12);

#define SPLIT_BUTTERFLY(p0,p1,p2,p3,p4,p5,p6,p7,p8,p9,z) \
    float v0, v1, v2, v3, v4; \
    { \
        float q, t; \
        q = h4 ? p0 : p5; t = __shfl_xor_sync(0xffffffffu, q, 16); v0 = (h4 ? p5 : p0) + t; \
        q = h4 ? p1 : p6; t = __shfl_xor_sync(0xffffffffu, q, 16); v1 = (h4 ? p6 : p1) + t; \
        q = h4 ? p2 : p7; t = __shfl_xor_sync(0xffffffffu, q, 16); v2 = (h4 ? p7 : p2) + t; \
        q = h4 ? p3 : p8; t = __shfl_xor_sync(0xffffffffu, q, 16); v3 = (h4 ? p8 : p3) + t; \
        q = h4 ? p4 : p9; t = __shfl_xor_sync(0xffffffffu, q, 16); v4 = (h4 ? p9 : p4) + t; \
    } \
    float w0, w1, w2; \
    { \
        float q0 = h3 ? v0 : v3; \
        float q1 = h3 ? v1 : v4; \
        float q2 = v2; \
        float t0s = __shfl_xor_sync(0xffffffffu, q0, 8); \
        float t1s = __shfl_xor_sync(0xffffffffu, q1, 8); \
        float t2s = __shfl_xor_sync(0xffffffffu, q2, 8); \
        if (!h3) { w0 = v0 + t0s; w1 = v1 + t1s; w2 = v2 + t2s; } \
        else     { w0 = v3 + t0s; w1 = v4 + t1s; w2 = 0.f; } \
    } \
    float u0, u1; \
    { \
        float q0 = h2 ? w0 : (h3 ? w1 : w2); \
        float q1 = w1; \
        float t0s = __shfl_xor_sync(0xffffffffu, q0, 4); \
        float t1s = __shfl_xor_sync(0xffffffffu, q1, 4); \
        if (!h3) { \
            if (!h2) { u0 = w0 + t0s; u1 = w1 + t1s; } \
            else     { u0 = w2 + t0s; u1 = 0.f; } \
        } else { \
            u0 = (h2 ? w1 : w0) + t0s; u1 = 0.f; \
        } \
    } \
    { \
        float q = two ? (h1 ? u0 : u1) : u0; \
        float t = __shfl_xor_sync(0xffffffffu, q, 2); \
        z = (two ? (h1 ? u1 : u0) : u0) + t; \
    } \
    z += __shfl_xor_sync(0xffffffffu, z, 1);

// ---- stage 2 (sigma0, K=7): float2 channels, warp = whole channel set -------
// Pointer-walking loads on the padded layout: no guards, no IMAD.WIDE chains.
template<int R, int SEGH, int NCH>
__global__ void __launch_bounds__(256) stage2(int) {
    constexpr int K = 2*R + 1;
    static_assert(SEGH == NCH*K, "strip must be multiple of K");
    const int tid  = threadIdx.x;
    const int warp = tid >> 5, lane = tid & 31;
    const int b    = blockIdx.z;
    const int x    = blockIdx.x*8 + warp;
    const int ys   = blockIdx.y*SEGH;
    const int rs2  = WW*32;                 // row stride in float2 units
    const size_t lo = (size_t)(PADT + ys - R)*rs2 + x*32 + lane;
    const float2* P0 = (const float2*)&g_X[(size_t)(0*BB + b)*XSTR] + lo;
    const float2* P1 = (const float2*)&g_X[(size_t)(1*BB + b)*XSTR] + lo;
    const float2* P2 = (const float2*)&g_X[(size_t)(2*BB + b)*XSTR] + lo;

    float4 fe[R+1]; float2 fo[R];
    #pragma unroll
    for (int t = 0; t <= R; ++t) fe[t] = g_fe[0][t];
    #pragma unroll
    for (int t = 0; t <  R; ++t) fo[t] = g_fo[0][t];

    REDUCE_ROUTING();
    float* PbW = &g_P0[(size_t)eidx*BHW + (size_t)b*HH*WW + (size_t)ys*WW + x];

    float2 r0[K], r1[K], r2[K];
    #pragma unroll
    for (int j = 0; j < K - 1; ++j) {
        const int sl = (j + K - R) % K;
        r0[sl] = *P0; P0 += rs2;
        r1[sl] = *P1; P1 += rs2;
        r2[sl] = *P2; P2 += rs2;
    }
    float2 t0 = *P0, t1 = *P1, t2 = *P2;
    P0 += rs2; P1 += rs2; P2 += rs2;

    int y = ys;
    for (int ch = 0; ch < NCH; ++ch) {
        #pragma unroll
        for (int i = 0; i < K; ++i, ++y) {
            {
                const int slN = (i + R) % K;
                r0[slN] = t0; r1[slN] = t1; r2[slN] = t2;
            }
            t0 = *P0; t1 = *P1; t2 = *P2;
            P0 += rs2; P1 += rs2; P2 += rs2;
            float2 L0={0.f,0.f}, L1=L0, L2=L0, L3=L0, L4=L0, L5=L0;
            #pragma unroll
            for (int j = 0; j < R; ++j) {
                const int sa = (i + j + (K - R)) % K;
                const int sb = (i + (K - 1 - j) + (K - R)) % K;
                float2 a0 = r0[sa], b0 = r0[sb];
                float2 a1 = r1[sa], b1 = r1[sb];
                float2 a2 = r2[sa], b2 = r2[sb];
                float s0x = a0.x + b0.x, s0y = a0.y + b0.y;
                float d0x = a0.x - b0.x, d0y = a0.y - b0.y;
                float s1x = a1.x + b1.x, s1y = a1.y + b1.y;
                float d1x = a1.x - b1.x, d1y = a1.y - b1.y;
                float s2x = a2.x + b2.x, s2y = a2.y + b2.y;
                L0.x = fmaf(fe[j].x, s0x, L0.x); L0.y = fmaf(fe[j].x, s0y, L0.y);
                L3.x = fmaf(fe[j].y, s0x, L3.x); L3.y = fmaf(fe[j].y, s0y, L3.y);
                L2.x = fmaf(fe[j].z, s1x, L2.x); L2.y = fmaf(fe[j].z, s1y, L2.y);
                L5.x = fmaf(fe[j].w, s2x, L5.x); L5.y = fmaf(fe[j].w, s2y, L5.y);
                L1.x = fmaf(fo[j].x, d0x, L1.x); L1.y = fmaf(fo[j].x, d0y, L1.y);
                L4.x = fmaf(fo[j].y, d1x, L4.x); L4.y = fmaf(fo[j].y, d1y, L4.y);
            }
            {
                L0.x = fmaf(fe[R].x, r0[i].x, L0.x); L0.y = fmaf(fe[R].x, r0[i].y, L0.y);
                L3.x = fmaf(fe[R].y, r0[i].x, L3.x); L3.y = fmaf(fe[R].y, r0[i].y, L3.y);
                L2.x = fmaf(fe[R].z, r1[i].x, L2.x); L2.y = fmaf(fe[R].z, r1[i].y, L2.y);
                L5.x = fmaf(fe[R].w, r2[i].x, L5.x); L5.y = fmaf(fe[R].w, r2[i].y, L5.y);
            }
            float p0 = fmaf(L0.y, L0.y, L0.x*L0.x);
            float p1 = fmaf(L1.y, L1.y, L1.x*L1.x);
            float p2 = fmaf(L1.y, L2.y, L1.x*L2.x);
            float p3 = fmaf(L2.y, L2.y, L2.x*L2.x);
            float p4 = fmaf(L3.y, L3.y, L3.x*L3.x);
            float p5 = fmaf(L3.y, L4.y, L3.x*L4.x);
            float p6 = fmaf(L3.y, L5.y, L3.x*L5.x);
            float p7 = fmaf(L4.y, L4.y, L4.x*L4.x);
            float p8 = fmaf(L4.y, L5.y, L4.x*L5.x);
            float p9 = fmaf(L5.y, L5.y, L5.x*L5.x);
            float z;
            SPLIT_BUTTERFLY(p0,p1,p2,p3,p4,p5,p6,p7,p8,p9,z);
            if (writer && y < HH)
                *PbW = z;
            PbW += WW;
        }
    }
}

// ---- stage 2w (sigma1, K=13): 1 channel/lane, 2 warps per x (chalf split) ---
template<int R, int SEGH, int NCH>
__global__ void __launch_bounds__(256, 2) stage2w(int) {
    constexpr int K = 2*R + 1;
    static_assert(SEGH == NCH*K, "strip must be multiple of K");
    const int tid  = threadIdx.x;
    const int warp = tid >> 5, lane = tid & 31;
    const int xi   = warp >> 1, chalf = warp & 1;
    const int b    = blockIdx.z;
    const int x    = blockIdx.x*4 + xi;
    const int ys   = blockIdx.y*SEGH;
    const int rs   = WW*CC;
    const size_t lo = (size_t)(PADT + ys - R)*rs + (size_t)x*CC + chalf*32 + lane;
    const float* P0 = &g_X[(size_t)(3*BB + b)*XSTR] + lo;
    const float* P1 = &g_X[(size_t)(4*BB + b)*XSTR] + lo;
    const float* P2 = &g_X[(size_t)(5*BB + b)*XSTR] + lo;

    float4 fe[R+1]; float2 fo[R];
    #pragma unroll
    for (int t = 0; t <= R; ++t) fe[t] = g_fe[1][t];
    #pragma unroll
    for (int t = 0; t <  R; ++t) fo[t] = g_fo[1][t];

    REDUCE_ROUTING();
    float* PbW = &g_P1[(size_t)(eidx*2 + chalf)*BHW + (size_t)b*HH*WW + (size_t)ys*WW + x];

    float r0[K], r1[K], r2[K];
    #pragma unroll
    for (int j = 0; j < K - 1; ++j) {
        const int sl = (j + K - R) % K;
        r0[sl] = *P0; P0 += rs;
        r1[sl] = *P1; P1 += rs;
        r2[sl] = *P2; P2 += rs;
    }
    float t0 = *P0, t1 = *P1, t2 = *P2;
    P0 += rs; P1 += rs; P2 += rs;

    int y = ys;
    for (int ch = 0; ch < NCH; ++ch) {
        #pragma unroll
        for (int i = 0; i < K; ++i, ++y) {
            {
                const int slN = (i + R) % K;
                r0[slN] = t0; r1[slN] = t1; r2[slN] = t2;
            }
            t0 = *P0; t1 = *P1; t2 = *P2;
            P0 += rs; P1 += rs; P2 += rs;
            float L0=0.f, L1=0.f, L2=0.f, L3=0.f, L4=0.f, L5=0.f;
            #pragma unroll
            for (int j = 0; j < R; ++j) {
                const int sa = (i + j + (K - R)) % K;
                const int sb = (i + (K - 1 - j) + (K - R)) % K;
                float s0 = r0[sa] + r0[sb], d0 = r0[sa] - r0[sb];
                float s1 = r1[sa] + r1[sb], d1 = r1[sa] - r1[sb];
                float s2 = r2[sa] + r2[sb];
                L0 = fmaf(fe[j].x, s0, L0);
                L3 = fmaf(fe[j].y, s0, L3);
                L2 = fmaf(fe[j].z, s1, L2);
                L5 = fmaf(fe[j].w, s2, L5);
                L1 = fmaf(fo[j].x, d0, L1);
                L4 = fmaf(fo[j].y, d1, L4);
            }
            {
                L0 = fmaf(fe[R].x, r0[i], L0);
                L3 = fmaf(fe[R].y, r0[i], L3);
                L2 = fmaf(fe[R].z, r1[i], L2);
                L5 = fmaf(fe[R].w, r2[i], L5);
            }
            float p0 = L0*L0, p1 = L1*L1, p2 = L1*L2, p3 = L2*L2, p4 = L3*L3;
            float p5 = L3*L4, p6 = L3*L5, p7 = L4*L4, p8 = L4*L5, p9 = L5*L5;
            float z;
            SPLIT_BUTTERFLY(p0,p1,p2,p3,p4,p5,p6,p7,p8,p9,z);
            if (writer && y < HH)
                *PbW = z;
            PbW += WW;
        }
    }
}

// ------- stage 3: separable 7x7 VALID integration + Newton-identity ESPs ----
__global__ void __launch_bounds__(256) stage3(float* __restrict__ out) {
    __shared__ float sP[10*22*22];
    __shared__ float sQ[10*22*16];
    const int tid = threadIdx.x;
    const int b = blockIdx.z;
    const int y0 = blockIdx.y*16, x0 = blockIdx.x*16;
    const int ty = tid >> 4, tx = tid & 15;
    const int yo = y0 + ty, xo = x0 + tx;
    const bool inb = (yo < HO) && (xo < HO);

    float wy[7], wx[7];
    #pragma unroll
    for (int i = 0; i < 7; ++i) { wy[i] = g_wy[i]; wx[i] = g_wx[i]; }

    float M[20];
    #pragma unroll
    for (int chunk = 0; chunk < 2; ++chunk) {
        for (int idx = tid; idx < 10*484; idx += 256) {
            int se  = idx / 484;
            int rem = idx - se*484;
            int r   = rem / 22;
            int cc2 = rem - r*22;
            int y = y0 + r, x = x0 + cc2;
            float v = 0.f;
            if (y < HH && x < WW) {
                size_t pix = (size_t)(b*HH + y)*WW + x;
                if (chunk == 0) v = g_P0[(size_t)se*BHW + pix];
                else v = g_P1[(size_t)(se*2)*BHW + pix] + g_P1[(size_t)(se*2+1)*BHW + pix];
            }
            sP[idx] = v;
        }
        __syncthreads();
        for (int idx = tid; idx < 10*352; idx += 256) {
            int se  = idx / 352;
            int rem = idx - se*352;
            int r   = rem >> 4;
            int cx  = rem & 15;
            const float* row = &sP[se*484 + r*22 + cx];
            float a = 0.f;
            #pragma unroll
            for (int j = 0; j < 7; ++j) a = fmaf(wx[j], row[j], a);
            sQ[idx] = a;
        }
        __syncthreads();
        #pragma unroll
        for (int s = 0; s < 10; ++s) {
            float a = 0.f;
            const float* col = &sQ[s*352 + ty*16 + tx];
            #pragma unroll
            for (int i = 0; i < 7; ++i) a = fmaf(wy[i], col[i*16], a);
            M[chunk*10 + s] = a;
        }
        __syncthreads();
    }
    if (!inb) return;

    const float EPSF = 2.2204460492503131e-16f;
    float res[12];
    #pragma unroll
    for (int s = 0; s < 2; ++s) {
        const float* Ms = M + s*10;
        res[s*6 + 0] = fabsf(Ms[0]) + EPSF;
        {
            float a = Ms[1], bq = Ms[2], c2v = Ms[3];
            float p1 = a + c2v;
            float p2 = a*a + 2.f*bq*bq + c2v*c2v;
            float e1 = p1;
            float e2 = 0.5f*(p1*e1 - p2);
            res[s*6 + 1] = 10.f*(fabsf(e1) + EPSF);
            res[s*6 + 2] = 10.f*sqrtf(fabsf(e2) + EPSF);
        }
        {
            float a = Ms[4], bq = Ms[5], cq = Ms[6], d = Ms[7], e = Ms[8], f = Ms[9];
            float p1 = a + d + f;
            float p2 = a*a + d*d + f*f + 2.f*(bq*bq + cq*cq + e*e);
            float p3 = a*a*a + d*d*d + f*f*f
                     + 3.f*(a*(bq*bq + cq*cq) + d*(bq*bq + e*e) + f*(cq*cq + e*e))
                     + 6.f*bq*cq*e;
            float e1 = p1;
            float e2 = 0.5f*(p1*e1 - p2);
            float e3 = (p1*e2 - p2*e1 + p3)*(1.f/3.f);
            res[s*6 + 3] = 100.f*(fabsf(e1) + EPSF);
            res[s*6 + 4] = 100.f*sqrtf(fabsf(e2) + EPSF);
            res[s*6 + 5] = 100.f*cbrtf(fabsf(e3) + EPSF);
        }
    }
    float* op = out + ((size_t)(b*HO + yo)*HO + xo)*12;
    #pragma unroll
    for (int chn = 0; chn < 12; ++chn) op[chn] = res[chn];
}

// ---------------- launcher ---------------------------------------------------
extern "C" void kernel_launch(void* const* d_in, const int* in_sizes, int n_in,
                              void* d_out, int out_size) {
    const float* in  = (const float*)d_in[0];
    const float* k0  = (const float*)d_in[1];
    const float* k1  = (const float*)d_in[2];
    const float* dgi = (const float*)d_in[3];
    float* out = (float*)d_out;

    zero_pads<<<576, 256>>>();
    factorize<<<1, 256>>>(k0, k1, dgi);

    stage1_both<<<dim3(3, HH, BB), 256>>>(in);
    // sigma 0 (R=3): 8 warps = 8 x-cols; 7 strips of 28 = 4*7
    stage2<3, 28, 4><<<dim3(24, 7, BB), 256>>>(0);
    // sigma 1 (R=6): 8 warps = 4 x-cols x 2 chalf; 5 strips of 39 = 3*13
    stage2w<6, 39, 3><<<dim3(48, 5, BB), 256>>>(1);

    stage3<<<dim3(12, 12, BB), 256>>>(out);
}

// round 13
// speedup vs baseline: 1.1551x; 1.1551x over previous
#include <cuda_runtime.h>
#include <math.h>

#define BB 4
#define HH 192
#define WW 192
#define CC 64
#define HO 186
#define BHW (BB*HH*WW)          /* 147456 */
#define NELEM (BB*HH*WW*CC)     /* 9437184 */

// ---------------- scratch (device globals; no allocs allowed) ----------------
__device__ __align__(256) float g_X[6][NELEM]; // x-conv: [sigma*3+order]
__device__ float  g_P0[10*BHW];    // sigma0: [e][b*H*W] full channel sums
__device__ float  g_P1[10*2*BHW];  // sigma1: [e*2+chalf][b*H*W] half sums
__device__ float2 g_fxe[2][7];     // x-factors folded: (ord0, ord2) taps 0..R
__device__ float  g_fxo[2][6];     // x-factor order1 taps 0..R-1 (antisym)
__device__ float4 g_fe[2][7];      // y-factors even maps: (L0, L3, L2, L5)
__device__ float2 g_fo[2][6];      // y-factors odd  maps: (L1, L4)
__device__ float  g_wy[7];         // integrator y factor
__device__ float  g_wx[7];         // integrator x factor

// -------- factorization: parallel load to smem, warp argmax, tiny serial tail
__global__ void __launch_bounds__(256) factorize(const float* __restrict__ k0,
                                                 const float* __restrict__ k1,
                                                 const float* __restrict__ dgi) {
    __shared__ float sk[294 + 1014 + 49];
    __shared__ int   s_r0[7], s_c0[7];
    __shared__ float s_piv[7];
    float* sk0 = sk;
    float* sk1 = sk + 294;
    float* sdg = sk + 294 + 1014;
    const int tid = threadIdx.x;
    for (int i = tid; i < 294;  i += 256) sk0[i] = k0[(size_t)i*CC];
    for (int i = tid; i < 1014; i += 256) sk1[i] = k1[(size_t)i*CC];
    for (int i = tid; i < 49;   i += 256) sdg[i] = dgi[(size_t)i*CC];
    __syncthreads();

    const int warp = tid >> 5, lane = tid & 31;
    const int canon[3] = {0, 2, 5};
    if (warp < 7) {
        const float* base; int Ksz, n;
        if (warp < 3)      { base = sk0 + canon[warp]*49;        Ksz = 7;  n = 49;  }
        else if (warp < 6) { base = sk1 + canon[warp - 3]*169;   Ksz = 13; n = 169; }
        else               { base = sdg;                          Ksz = 7;  n = 49;  }
        float best = -1.f; int bidx = 0;
        for (int i = lane; i < n; i += 32) {
            float v = fabsf(base[i]);
            if (v > best) { best = v; bidx = i; }
        }
        #pragma unroll
        for (int off = 16; off >= 1; off >>= 1) {
            float ob = __shfl_xor_sync(0xffffffffu, best, off);
            int   oi = __shfl_xor_sync(0xffffffffu, bidx, off);
            if (ob > best || (ob == best && oi < bidx)) { best = ob; bidx = oi; }
        }
        if (lane == 0) {
            s_r0[warp] = bidx / Ksz; s_c0[warp] = bidx % Ksz; s_piv[warp] = base[bidx];
        }
    }
    __syncthreads();

    if (tid != 0) return;
    const int kxo[6]  = {0, 0, 1, 0, 1, 2};
    const float comb[6] = {1.f, 1.f, 1.f, 1.f, 1.41421356237309515f, 1.f};
    for (int s = 0; s < 2; ++s) {
        const float* skb = s ? sk1 : sk0;
        const int Ksz = s ? 13 : 7, R = (Ksz - 1)/2, per = Ksz*Ksz;
        float fx[3][13]; int c0s[3];
        for (int o = 0; o < 3; ++o) {
            const int task = s*3 + o;
            const int r0 = s_r0[task]; c0s[o] = s_c0[task];
            const float piv = s_piv[task];
            const float* Km = skb + canon[o]*per;
            for (int j = 0; j < Ksz; ++j) fx[o][j] = Km[r0*Ksz + j] / piv;
        }
        for (int t = 0; t <= R; ++t) g_fxe[s][t] = make_float2(fx[0][t], fx[2][t]);
        for (int t = 0; t <  R; ++t) g_fxo[s][t] = fx[1][t];
        float fy[6][13];
        for (int m = 0; m < 6; ++m) {
            const int c0 = c0s[kxo[m]];
            for (int i = 0; i < Ksz; ++i) fy[m][i] = skb[m*per + i*Ksz + c0] * comb[m];
        }
        for (int t = 0; t <= R; ++t)
            g_fe[s][t] = make_float4(fy[0][t], fy[3][t], fy[2][t], fy[5][t]);
        for (int t = 0; t <  R; ++t)
            g_fo[s][t] = make_float2(fy[1][t], fy[4][t]);
    }
    {
        const int r0 = s_r0[6], c0 = s_c0[6]; const float piv = s_piv[6];
        for (int i = 0; i < 7; ++i) g_wy[i] = sdg[i*7 + c0];
        for (int j = 0; j < 7; ++j) g_wx[j] = sdg[r0*7 + j] / piv;
    }
}

// ------- stage 1 (merged): x-convs for BOTH sigmas, orders 0..2 each --------
__global__ void __launch_bounds__(256) stage1_both(const float* __restrict__ in) {
    constexpr int XT = 64;
    __shared__ float2 s_in[(XT + 12)*32];
    const int b = blockIdx.z, yrow = blockIdx.y, x0 = blockIdx.x*XT;
    const int tid = threadIdx.x;
    const float2* rowv = (const float2*)(in + ((size_t)(b*HH + yrow)*WW)*CC);
    for (int t = tid; t < (XT + 12)*32; t += 256) {
        int xx = (t >> 5) - 6 + x0;
        int c2 = t & 31;
        s_in[t] = (xx >= 0 && xx < WW) ? rowv[xx*32 + c2] : make_float2(0.f, 0.f);
    }
    float2 fxe0[4], fxe1[7]; float fxo0[3], fxo1[6];
    #pragma unroll
    for (int t = 0; t < 4; ++t) fxe0[t] = g_fxe[0][t];
    #pragma unroll
    for (int t = 0; t < 3; ++t) fxo0[t] = g_fxo[0][t];
    #pragma unroll
    for (int t = 0; t < 7; ++t) fxe1[t] = g_fxe[1][t];
    #pragma unroll
    for (int t = 0; t < 6; ++t) fxo1[t] = g_fxo[1][t];
    __syncthreads();

    const int c2 = tid & 31, xg = tid >> 5;
    const size_t obase = ((size_t)(b*HH + yrow)*WW)*CC;
    float2* o00 = (float2*)&g_X[0][obase];
    float2* o01 = (float2*)&g_X[1][obase];
    float2* o02 = (float2*)&g_X[2][obase];
    float2* o10 = (float2*)&g_X[3][obase];
    float2* o11 = (float2*)&g_X[4][obase];
    float2* o12 = (float2*)&g_X[5][obase];
    #pragma unroll
    for (int xq = 0; xq < 8; ++xq) {
        int xi = xg*8 + xq;
        float2 A0={0.f,0.f}, A1={0.f,0.f}, A2={0.f,0.f};
        float2 B0={0.f,0.f}, B1={0.f,0.f}, B2={0.f,0.f};
        #pragma unroll
        for (int t = 0; t < 6; ++t) {
            float2 u = s_in[(xi + t)*32 + c2];
            float2 v = s_in[(xi + 12 - t)*32 + c2];
            float sx = u.x + v.x, sy = u.y + v.y;
            float dx = u.x - v.x, dy = u.y - v.y;
            B0.x = fmaf(fxe1[t].x, sx, B0.x); B0.y = fmaf(fxe1[t].x, sy, B0.y);
            B2.x = fmaf(fxe1[t].y, sx, B2.x); B2.y = fmaf(fxe1[t].y, sy, B2.y);
            B1.x = fmaf(fxo1[t],   dx, B1.x); B1.y = fmaf(fxo1[t],   dy, B1.y);
            if (t >= 3) {
                const int t0 = t - 3;
                A0.x = fmaf(fxe0[t0].x, sx, A0.x); A0.y = fmaf(fxe0[t0].x, sy, A0.y);
                A2.x = fmaf(fxe0[t0].y, sx, A2.x); A2.y = fmaf(fxe0[t0].y, sy, A2.y);
                A1.x = fmaf(fxo0[t0],   dx, A1.x); A1.y = fmaf(fxo0[t0],   dy, A1.y);
            }
        }
        float2 m = s_in[(xi + 6)*32 + c2];
        B0.x = fmaf(fxe1[6].x, m.x, B0.x); B0.y = fmaf(fxe1[6].x, m.y, B0.y);
        B2.x = fmaf(fxe1[6].y, m.x, B2.x); B2.y = fmaf(fxe1[6].y, m.y, B2.y);
        A0.x = fmaf(fxe0[3].x, m.x, A0.x); A0.y = fmaf(fxe0[3].x, m.y, A0.y);
        A2.x = fmaf(fxe0[3].y, m.x, A2.x); A2.y = fmaf(fxe0[3].y, m.y, A2.y);
        int off = (x0 + xi)*32 + c2;
        o00[off] = A0; o01[off] = A1; o02[off] = A2;
        o10[off] = B0; o11[off] = B1; o12[off] = B2;
    }
}

// ---- reduction routing shared by both stage2 bodies -------------------------
#define REDUCE_ROUTING() \
    const bool h4 = (lane & 16) != 0; \
    const bool h3 = (lane & 8)  != 0; \
    const bool h2 = (lane & 4)  != 0; \
    const bool h1 = (lane & 2)  != 0; \
    const bool two = (!h3) && (!h2); \
    const int  m4 = lane & 15; \
    const int  f  = (m4==0) ? 0 : (m4==2) ? 1 : (m4==4) ? 2 : (m4==8) ? 3 : 4; \
    const int  eidx = (h4 ? 5 : 0) + f; \
    const bool writer = (m4==0 || m4==2 || m4==4 || m4==8 || m4==12);

#define SPLIT_BUTTERFLY(p0,p1,p2,p3,p4,p5,p6,p7,p8,p9,z) \
    float v0, v1, v2, v3, v4; \
    { \
        float q, t; \
        q = h4 ? p0 : p5; t = __shfl_xor_sync(0xffffffffu, q, 16); v0 = (h4 ? p5 : p0) + t; \
        q = h4 ? p1 : p6; t = __shfl_xor_sync(0xffffffffu, q, 16); v1 = (h4 ? p6 : p1) + t; \
        q = h4 ? p2 : p7; t = __shfl_xor_sync(0xffffffffu, q, 16); v2 = (h4 ? p7 : p2) + t; \
        q = h4 ? p3 : p8; t = __shfl_xor_sync(0xffffffffu, q, 16); v3 = (h4 ? p8 : p3) + t; \
        q = h4 ? p4 : p9; t = __shfl_xor_sync(0xffffffffu, q, 16); v4 = (h4 ? p9 : p4) + t; \
    } \
    float w0, w1, w2; \
    { \
        float q0 = h3 ? v0 : v3; \
        float q1 = h3 ? v1 : v4; \
        float q2 = v2; \
        float t0s = __shfl_xor_sync(0xffffffffu, q0, 8); \
        float t1s = __shfl_xor_sync(0xffffffffu, q1, 8); \
        float t2s = __shfl_xor_sync(0xffffffffu, q2, 8); \
        if (!h3) { w0 = v0 + t0s; w1 = v1 + t1s; w2 = v2 + t2s; } \
        else     { w0 = v3 + t0s; w1 = v4 + t1s; w2 = 0.f; } \
    } \
    float u0, u1; \
    { \
        float q0 = h2 ? w0 : (h3 ? w1 : w2); \
        float q1 = w1; \
        float t0s = __shfl_xor_sync(0xffffffffu, q0, 4); \
        float t1s = __shfl_xor_sync(0xffffffffu, q1, 4); \
        if (!h3) { \
            if (!h2) { u0 = w0 + t0s; u1 = w1 + t1s; } \
            else     { u0 = w2 + t0s; u1 = 0.f; } \
        } else { \
            u0 = (h2 ? w1 : w0) + t0s; u1 = 0.f; \
        } \
    } \
    { \
        float q = two ? (h1 ? u0 : u1) : u0; \
        float t = __shfl_xor_sync(0xffffffffu, q, 2); \
        z = (two ? (h1 ? u1 : u0) : u0) + t; \
    } \
    z += __shfl_xor_sync(0xffffffffu, z, 1);

// ---- sigma0 body (K=7): float2 channels, warp = whole channel set -----------
template<int R, int SEGH, int NCH>
__device__ __forceinline__ void s2_body0(int bxi, int byi, int b, int tid) {
    constexpr int K = 2*R + 1;
    const int warp = tid >> 5, lane = tid & 31;
    const int x    = bxi*8 + warp;
    const int ys   = byi*SEGH;
    const int rs   = WW*32;
    const size_t base = ((size_t)(b*HH*WW) + x)*32 + lane;
    const float2* X0 = (const float2*)g_X[0] + base;
    const float2* X1 = (const float2*)g_X[1] + base;
    const float2* X2 = (const float2*)g_X[2] + base;

    float4 fe[R+1]; float2 fo[R];
    #pragma unroll
    for (int t = 0; t <= R; ++t) fe[t] = g_fe[0][t];
    #pragma unroll
    for (int t = 0; t <  R; ++t) fo[t] = g_fo[0][t];

    REDUCE_ROUTING();
    float* PbE = &g_P0[(size_t)eidx*BHW + (size_t)b*HH*WW + x];

    const float2 Z2 = make_float2(0.f, 0.f);
    float2 r0[K], r1[K], r2[K];
    #pragma unroll
    for (int j = 0; j < K - 1; ++j) {
        int yy = ys - R + j;
        const int sl = (j + K - R) % K;
        bool ok = (yy >= 0 && yy < HH);
        r0[sl] = ok ? X0[(size_t)yy*rs] : Z2;
        r1[sl] = ok ? X1[(size_t)yy*rs] : Z2;
        r2[sl] = ok ? X2[(size_t)yy*rs] : Z2;
    }
    float2 t0, t1, t2;
    {
        int yy = ys + R;
        bool ok = yy < HH;
        t0 = ok ? X0[(size_t)yy*rs] : Z2;
        t1 = ok ? X1[(size_t)yy*rs] : Z2;
        t2 = ok ? X2[(size_t)yy*rs] : Z2;
    }

    int y = ys;
    for (int ch = 0; ch < NCH; ++ch) {
        #pragma unroll
        for (int i = 0; i < K; ++i, ++y) {
            {
                const int slN = (i + R) % K;
                r0[slN] = t0; r1[slN] = t1; r2[slN] = t2;
            }
            {
                int yy = y + 1 + R;
                bool ok = yy < HH;
                t0 = ok ? X0[(size_t)yy*rs] : Z2;
                t1 = ok ? X1[(size_t)yy*rs] : Z2;
                t2 = ok ? X2[(size_t)yy*rs] : Z2;
            }
            float2 L0=Z2, L1=Z2, L2=Z2, L3=Z2, L4=Z2, L5=Z2;
            #pragma unroll
            for (int j = 0; j < R; ++j) {
                const int sa = (i + j + (K - R)) % K;
                const int sb = (i + (K - 1 - j) + (K - R)) % K;
                float2 a0 = r0[sa], b0 = r0[sb];
                float2 a1 = r1[sa], b1 = r1[sb];
                float2 a2 = r2[sa], b2 = r2[sb];
                float s0x = a0.x + b0.x, s0y = a0.y + b0.y;
                float d0x = a0.x - b0.x, d0y = a0.y - b0.y;
                float s1x = a1.x + b1.x, s1y = a1.y + b1.y;
                float d1x = a1.x - b1.x, d1y = a1.y - b1.y;
                float s2x = a2.x + b2.x, s2y = a2.y + b2.y;
                L0.x = fmaf(fe[j].x, s0x, L0.x); L0.y = fmaf(fe[j].x, s0y, L0.y);
                L3.x = fmaf(fe[j].y, s0x, L3.x); L3.y = fmaf(fe[j].y, s0y, L3.y);
                L2.x = fmaf(fe[j].z, s1x, L2.x); L2.y = fmaf(fe[j].z, s1y, L2.y);
                L5.x = fmaf(fe[j].w, s2x, L5.x); L5.y = fmaf(fe[j].w, s2y, L5.y);
                L1.x = fmaf(fo[j].x, d0x, L1.x); L1.y = fmaf(fo[j].x, d0y, L1.y);
                L4.x = fmaf(fo[j].y, d1x, L4.x); L4.y = fmaf(fo[j].y, d1y, L4.y);
            }
            {
                L0.x = fmaf(fe[R].x, r0[i].x, L0.x); L0.y = fmaf(fe[R].x, r0[i].y, L0.y);
                L3.x = fmaf(fe[R].y, r0[i].x, L3.x); L3.y = fmaf(fe[R].y, r0[i].y, L3.y);
                L2.x = fmaf(fe[R].z, r1[i].x, L2.x); L2.y = fmaf(fe[R].z, r1[i].y, L2.y);
                L5.x = fmaf(fe[R].w, r2[i].x, L5.x); L5.y = fmaf(fe[R].w, r2[i].y, L5.y);
            }
            float p0 = fmaf(L0.y, L0.y, L0.x*L0.x);
            float p1 = fmaf(L1.y, L1.y, L1.x*L1.x);
            float p2 = fmaf(L1.y, L2.y, L1.x*L2.x);
            float p3 = fmaf(L2.y, L2.y, L2.x*L2.x);
            float p4 = fmaf(L3.y, L3.y, L3.x*L3.x);
            float p5 = fmaf(L3.y, L4.y, L3.x*L4.x);
            float p6 = fmaf(L3.y, L5.y, L3.x*L5.x);
            float p7 = fmaf(L4.y, L4.y, L4.x*L4.x);
            float p8 = fmaf(L4.y, L5.y, L4.x*L5.x);
            float p9 = fmaf(L5.y, L5.y, L5.x*L5.x);
            float z;
            SPLIT_BUTTERFLY(p0,p1,p2,p3,p4,p5,p6,p7,p8,p9,z);
            if (writer && y < HH)
                PbE[y*WW] = z;
        }
    }
}

// ---- sigma1 body (K=13): 1 channel/lane, 2 warps per x (chalf split) --------
template<int R, int SEGH, int NCH>
__device__ __forceinline__ void s2_body1(int bxi, int byi, int b, int tid) {
    constexpr int K = 2*R + 1;
    const int warp = tid >> 5, lane = tid & 31;
    const int xi   = warp >> 1, chalf = warp & 1;
    const int x    = bxi*4 + xi;
    const int ys   = byi*SEGH;
    const int rs   = WW*CC;
    const size_t base = ((size_t)(b*HH*WW) + x)*CC + chalf*32 + lane;
    const float* X0 = g_X[3] + base;
    const float* X1 = g_X[4] + base;
    const float* X2 = g_X[5] + base;

    float4 fe[R+1]; float2 fo[R];
    #pragma unroll
    for (int t = 0; t <= R; ++t) fe[t] = g_fe[1][t];
    #pragma unroll
    for (int t = 0; t <  R; ++t) fo[t] = g_fo[1][t];

    REDUCE_ROUTING();
    float* PbE = &g_P1[(size_t)(eidx*2 + chalf)*BHW + (size_t)b*HH*WW + x];

    float r0[K], r1[K], r2[K];
    #pragma unroll
    for (int j = 0; j < K - 1; ++j) {
        int yy = ys - R + j;
        const int sl = (j + K - R) % K;
        bool ok = (yy >= 0 && yy < HH);
        r0[sl] = ok ? X0[(size_t)yy*rs] : 0.f;
        r1[sl] = ok ? X1[(size_t)yy*rs] : 0.f;
        r2[sl] = ok ? X2[(size_t)yy*rs] : 0.f;
    }
    float t0, t1, t2;
    {
        int yy = ys + R;
        bool ok = yy < HH;
        t0 = ok ? X0[(size_t)yy*rs] : 0.f;
        t1 = ok ? X1[(size_t)yy*rs] : 0.f;
        t2 = ok ? X2[(size_t)yy*rs] : 0.f;
    }

    int y = ys;
    for (int ch = 0; ch < NCH; ++ch) {
        #pragma unroll
        for (int i = 0; i < K; ++i, ++y) {
            {
                const int slN = (i + R) % K;
                r0[slN] = t0; r1[slN] = t1; r2[slN] = t2;
            }
            {
                int yy = y + 1 + R;
                bool ok = yy < HH;
                t0 = ok ? X0[(size_t)yy*rs] : 0.f;
                t1 = ok ? X1[(size_t)yy*rs] : 0.f;
                t2 = ok ? X2[(size_t)yy*rs] : 0.f;
            }
            float L0=0.f, L1=0.f, L2=0.f, L3=0.f, L4=0.f, L5=0.f;
            #pragma unroll
            for (int j = 0; j < R; ++j) {
                const int sa = (i + j + (K - R)) % K;
                const int sb = (i + (K - 1 - j) + (K - R)) % K;
                float s0 = r0[sa] + r0[sb], d0 = r0[sa] - r0[sb];
                float s1 = r1[sa] + r1[sb], d1 = r1[sa] - r1[sb];
                float s2 = r2[sa] + r2[sb];
                L0 = fmaf(fe[j].x, s0, L0);
                L3 = fmaf(fe[j].y, s0, L3);
                L2 = fmaf(fe[j].z, s1, L2);
                L5 = fmaf(fe[j].w, s2, L5);
                L1 = fmaf(fo[j].x, d0, L1);
                L4 = fmaf(fo[j].y, d1, L4);
            }
            {
                L0 = fmaf(fe[R].x, r0[i], L0);
                L3 = fmaf(fe[R].y, r0[i], L3);
                L2 = fmaf(fe[R].z, r1[i], L2);
                L5 = fmaf(fe[R].w, r2[i], L5);
            }
            float p0 = L0*L0, p1 = L1*L1, p2 = L1*L2, p3 = L2*L2, p4 = L3*L3;
            float p5 = L3*L4, p6 = L3*L5, p7 = L4*L4, p8 = L4*L5, p9 = L5*L5;
            float z;
            SPLIT_BUTTERFLY(p0,p1,p2,p3,p4,p5,p6,p7,p8,p9,z);
            if (writer && y < HH)
                PbE[y*WW] = z;
        }
    }
}

// ---- fused stage 2: sigma1 blocks first (longest), sigma0 backfills ---------
#define S1_BLOCKS (48*5*BB)   /* 960 */
#define S0_BLOCKS (24*7*BB)   /* 672 */
__global__ void __launch_bounds__(256, 2) stage2_fused() {
    const int tid = threadIdx.x;
    int blk = blockIdx.x;
    if (blk < S1_BLOCKS) {
        int bxi = blk % 48, r = blk / 48;
        s2_body1<6, 39, 3>(bxi, r % 5, r / 5, tid);
    } else {
        blk -= S1_BLOCKS;
        int bxi = blk % 24, r = blk / 24;
        s2_body0<3, 28, 4>(bxi, r % 7, r / 7, tid);
    }
}

// ------- stage 3: separable 7x7 VALID integration + Newton-identity ESPs ----
__global__ void __launch_bounds__(256) stage3(float* __restrict__ out) {
    __shared__ float sP[10*22*22];
    __shared__ float sQ[10*22*16];
    const int tid = threadIdx.x;
    const int b = blockIdx.z;
    const int y0 = blockIdx.y*16, x0 = blockIdx.x*16;
    const int ty = tid >> 4, tx = tid & 15;
    const int yo = y0 + ty, xo = x0 + tx;
    const bool inb = (yo < HO) && (xo < HO);

    float wy[7], wx[7];
    #pragma unroll
    for (int i = 0; i < 7; ++i) { wy[i] = g_wy[i]; wx[i] = g_wx[i]; }

    float M[20];
    #pragma unroll
    for (int chunk = 0; chunk < 2; ++chunk) {
        for (int idx = tid; idx < 10*484; idx += 256) {
            int se  = idx / 484;
            int rem = idx - se*484;
            int r   = rem / 22;
            int cc2 = rem - r*22;
            int y = y0 + r, x = x0 + cc2;
            float v = 0.f;
            if (y < HH && x < WW) {
                size_t pix = (size_t)(b*HH + y)*WW + x;
                if (chunk == 0) v = g_P0[(size_t)se*BHW + pix];
                else v = g_P1[(size_t)(se*2)*BHW + pix] + g_P1[(size_t)(se*2+1)*BHW + pix];
            }
            sP[idx] = v;
        }
        __syncthreads();
        for (int idx = tid; idx < 10*352; idx += 256) {
            int se  = idx / 352;
            int rem = idx - se*352;
            int r   = rem >> 4;
            int cx  = rem & 15;
            const float* row = &sP[se*484 + r*22 + cx];
            float a = 0.f;
            #pragma unroll
            for (int j = 0; j < 7; ++j) a = fmaf(wx[j], row[j], a);
            sQ[idx] = a;
        }
        __syncthreads();
        #pragma unroll
        for (int s = 0; s < 10; ++s) {
            float a = 0.f;
            const float* col = &sQ[s*352 + ty*16 + tx];
            #pragma unroll
            for (int i = 0; i < 7; ++i) a = fmaf(wy[i], col[i*16], a);
            M[chunk*10 + s] = a;
        }
        __syncthreads();
    }
    if (!inb) return;

    const float EPSF = 2.2204460492503131e-16f;
    float res[12];
    #pragma unroll
    for (int s = 0; s < 2; ++s) {
        const float* Ms = M + s*10;
        res[s*6 + 0] = fabsf(Ms[0]) + EPSF;
        {
            float a = Ms[1], bq = Ms[2], c2v = Ms[3];
            float p1 = a + c2v;
            float p2 = a*a + 2.f*bq*bq + c2v*c2v;
            float e1 = p1;
            float e2 = 0.5f*(p1*e1 - p2);
            res[s*6 + 1] = 10.f*(fabsf(e1) + EPSF);
            res[s*6 + 2] = 10.f*sqrtf(fabsf(e2) + EPSF);
        }
        {
            float a = Ms[4], bq = Ms[5], cq = Ms[6], d = Ms[7], e = Ms[8], f = Ms[9];
            float p1 = a + d + f;
            float p2 = a*a + d*d + f*f + 2.f*(bq*bq + cq*cq + e*e);
            float p3 = a*a*a + d*d*d + f*f*f
                     + 3.f*(a*(bq*bq + cq*cq) + d*(bq*bq + e*e) + f*(cq*cq + e*e))
                     + 6.f*bq*cq*e;
            float e1 = p1;
            float e2 = 0.5f*(p1*e1 - p2);
            float e3 = (p1*e2 - p2*e1 + p3)*(1.f/3.f);
            res[s*6 + 3] = 100.f*(fabsf(e1) + EPSF);
            res[s*6 + 4] = 100.f*sqrtf(fabsf(e2) + EPSF);
            res[s*6 + 5] = 100.f*cbrtf(fabsf(e3) + EPSF);
        }
    }
    float* op = out + ((size_t)(b*HO + yo)*HO + xo)*12;
    #pragma unroll
    for (int chn = 0; chn < 12; ++chn) op[chn] = res[chn];
}

// ---------------- launcher ---------------------------------------------------
extern "C" void kernel_launch(void* const* d_in, const int* in_sizes, int n_in,
                              void* d_out, int out_size) {
    const float* in  = (const float*)d_in[0];
    const float* k0  = (const float*)d_in[1];
    const float* k1  = (const float*)d_in[2];
    const float* dgi = (const float*)d_in[3];
    float* out = (float*)d_out;

    factorize<<<1, 256>>>(k0, k1, dgi);
    stage1_both<<<dim3(3, HH, BB), 256>>>(in);
    stage2_fused<<<S1_BLOCKS + S0_BLOCKS, 256>>>();
    stage3<<<dim3(12, 12, BB), 256>>>(out);
}

// round 14
// speedup vs baseline: 1.1556x; 1.0005x over previous
#include <cuda_runtime.h>
#include <math.h>

#define BB 4
#define HH 192
#define WW 192
#define CC 64
#define HO 186
#define BHW (BB*HH*WW)          /* 147456 */
#define NELEM (BB*HH*WW*CC)     /* 9437184 */

// ---------------- scratch (device globals; no allocs allowed) ----------------
__device__ __align__(256) float g_X[6][NELEM]; // x-conv: [sigma*3+order]
__device__ float  g_P0[10*BHW];    // sigma0: [e][b*H*W] full channel sums
__device__ float  g_P1[10*2*BHW];  // sigma1: [e*2+chalf][b*H*W] half sums
__device__ float2 g_fxe[2][7];     // x-factors folded: (ord0, ord2) taps 0..R
__device__ float  g_fxo[2][6];     // x-factor order1 taps 0..R-1 (antisym)
__device__ float4 g_fe[2][7];      // y-factors even maps: (L0, L3, L2, L5)
__device__ float2 g_fo[2][6];      // y-factors odd  maps: (L1, L4)
__device__ float  g_wy[7];         // integrator y factor
__device__ float  g_wx[7];         // integrator x factor

// -------- factorization: parallel load to smem, warp argmax, tiny serial tail
__global__ void __launch_bounds__(256) factorize(const float* __restrict__ k0,
                                                 const float* __restrict__ k1,
                                                 const float* __restrict__ dgi) {
    __shared__ float sk[294 + 1014 + 49];
    __shared__ int   s_r0[7], s_c0[7];
    __shared__ float s_piv[7];
    float* sk0 = sk;
    float* sk1 = sk + 294;
    float* sdg = sk + 294 + 1014;
    const int tid = threadIdx.x;
    for (int i = tid; i < 294;  i += 256) sk0[i] = k0[(size_t)i*CC];
    for (int i = tid; i < 1014; i += 256) sk1[i] = k1[(size_t)i*CC];
    for (int i = tid; i < 49;   i += 256) sdg[i] = dgi[(size_t)i*CC];
    __syncthreads();

    const int warp = tid >> 5, lane = tid & 31;
    const int canon[3] = {0, 2, 5};
    if (warp < 7) {
        const float* base; int Ksz, n;
        if (warp < 3)      { base = sk0 + canon[warp]*49;        Ksz = 7;  n = 49;  }
        else if (warp < 6) { base = sk1 + canon[warp - 3]*169;   Ksz = 13; n = 169; }
        else               { base = sdg;                          Ksz = 7;  n = 49;  }
        float best = -1.f; int bidx = 0;
        for (int i = lane; i < n; i += 32) {
            float v = fabsf(base[i]);
            if (v > best) { best = v; bidx = i; }
        }
        #pragma unroll
        for (int off = 16; off >= 1; off >>= 1) {
            float ob = __shfl_xor_sync(0xffffffffu, best, off);
            int   oi = __shfl_xor_sync(0xffffffffu, bidx, off);
            if (ob > best || (ob == best && oi < bidx)) { best = ob; bidx = oi; }
        }
        if (lane == 0) {
            s_r0[warp] = bidx / Ksz; s_c0[warp] = bidx % Ksz; s_piv[warp] = base[bidx];
        }
    }
    __syncthreads();

    if (tid != 0) return;
    const int kxo[6]  = {0, 0, 1, 0, 1, 2};
    const float comb[6] = {1.f, 1.f, 1.f, 1.f, 1.41421356237309515f, 1.f};
    for (int s = 0; s < 2; ++s) {
        const float* skb = s ? sk1 : sk0;
        const int Ksz = s ? 13 : 7, R = (Ksz - 1)/2, per = Ksz*Ksz;
        float fx[3][13]; int c0s[3];
        for (int o = 0; o < 3; ++o) {
            const int task = s*3 + o;
            const int r0 = s_r0[task]; c0s[o] = s_c0[task];
            const float piv = s_piv[task];
            const float* Km = skb + canon[o]*per;
            for (int j = 0; j < Ksz; ++j) fx[o][j] = Km[r0*Ksz + j] / piv;
        }
        for (int t = 0; t <= R; ++t) g_fxe[s][t] = make_float2(fx[0][t], fx[2][t]);
        for (int t = 0; t <  R; ++t) g_fxo[s][t] = fx[1][t];
        float fy[6][13];
        for (int m = 0; m < 6; ++m) {
            const int c0 = c0s[kxo[m]];
            for (int i = 0; i < Ksz; ++i) fy[m][i] = skb[m*per + i*Ksz + c0] * comb[m];
        }
        for (int t = 0; t <= R; ++t)
            g_fe[s][t] = make_float4(fy[0][t], fy[3][t], fy[2][t], fy[5][t]);
        for (int t = 0; t <  R; ++t)
            g_fo[s][t] = make_float2(fy[1][t], fy[4][t]);
    }
    {
        const int r0 = s_r0[6], c0 = s_c0[6]; const float piv = s_piv[6];
        for (int i = 0; i < 7; ++i) g_wy[i] = sdg[i*7 + c0];
        for (int j = 0; j < 7; ++j) g_wx[j] = sdg[r0*7 + j] / piv;
    }
}

// ------- stage 1 (merged): x-convs for BOTH sigmas, orders 0..2 each --------
__global__ void __launch_bounds__(256) stage1_both(const float* __restrict__ in) {
    constexpr int XT = 64;
    __shared__ float2 s_in[(XT + 12)*32];
    const int b = blockIdx.z, yrow = blockIdx.y, x0 = blockIdx.x*XT;
    const int tid = threadIdx.x;
    const float2* rowv = (const float2*)(in + ((size_t)(b*HH + yrow)*WW)*CC);
    for (int t = tid; t < (XT + 12)*32; t += 256) {
        int xx = (t >> 5) - 6 + x0;
        int c2 = t & 31;
        s_in[t] = (xx >= 0 && xx < WW) ? rowv[xx*32 + c2] : make_float2(0.f, 0.f);
    }
    float2 fxe0[4], fxe1[7]; float fxo0[3], fxo1[6];
    #pragma unroll
    for (int t = 0; t < 4; ++t) fxe0[t] = g_fxe[0][t];
    #pragma unroll
    for (int t = 0; t < 3; ++t) fxo0[t] = g_fxo[0][t];
    #pragma unroll
    for (int t = 0; t < 7; ++t) fxe1[t] = g_fxe[1][t];
    #pragma unroll
    for (int t = 0; t < 6; ++t) fxo1[t] = g_fxo[1][t];
    __syncthreads();

    const int c2 = tid & 31, xg = tid >> 5;
    const size_t obase = ((size_t)(b*HH + yrow)*WW)*CC;
    float2* o00 = (float2*)&g_X[0][obase];
    float2* o01 = (float2*)&g_X[1][obase];
    float2* o02 = (float2*)&g_X[2][obase];
    float2* o10 = (float2*)&g_X[3][obase];
    float2* o11 = (float2*)&g_X[4][obase];
    float2* o12 = (float2*)&g_X[5][obase];
    #pragma unroll
    for (int xq = 0; xq < 8; ++xq) {
        int xi = xg*8 + xq;
        float2 A0={0.f,0.f}, A1={0.f,0.f}, A2={0.f,0.f};
        float2 B0={0.f,0.f}, B1={0.f,0.f}, B2={0.f,0.f};
        #pragma unroll
        for (int t = 0; t < 6; ++t) {
            float2 u = s_in[(xi + t)*32 + c2];
            float2 v = s_in[(xi + 12 - t)*32 + c2];
            float sx = u.x + v.x, sy = u.y + v.y;
            float dx = u.x - v.x, dy = u.y - v.y;
            B0.x = fmaf(fxe1[t].x, sx, B0.x); B0.y = fmaf(fxe1[t].x, sy, B0.y);
            B2.x = fmaf(fxe1[t].y, sx, B2.x); B2.y = fmaf(fxe1[t].y, sy, B2.y);
            B1.x = fmaf(fxo1[t],   dx, B1.x); B1.y = fmaf(fxo1[t],   dy, B1.y);
            if (t >= 3) {
                const int t0 = t - 3;
                A0.x = fmaf(fxe0[t0].x, sx, A0.x); A0.y = fmaf(fxe0[t0].x, sy, A0.y);
                A2.x = fmaf(fxe0[t0].y, sx, A2.x); A2.y = fmaf(fxe0[t0].y, sy, A2.y);
                A1.x = fmaf(fxo0[t0],   dx, A1.x); A1.y = fmaf(fxo0[t0],   dy, A1.y);
            }
        }
        float2 m = s_in[(xi + 6)*32 + c2];
        B0.x = fmaf(fxe1[6].x, m.x, B0.x); B0.y = fmaf(fxe1[6].x, m.y, B0.y);
        B2.x = fmaf(fxe1[6].y, m.x, B2.x); B2.y = fmaf(fxe1[6].y, m.y, B2.y);
        A0.x = fmaf(fxe0[3].x, m.x, A0.x); A0.y = fmaf(fxe0[3].x, m.y, A0.y);
        A2.x = fmaf(fxe0[3].y, m.x, A2.x); A2.y = fmaf(fxe0[3].y, m.y, A2.y);
        int off = (x0 + xi)*32 + c2;
        o00[off] = A0; o01[off] = A1; o02[off] = A2;
        o10[off] = B0; o11[off] = B1; o12[off] = B2;
    }
}

// ---- reduction routing shared by both stage2 bodies -------------------------
#define REDUCE_ROUTING() \
    const bool h4 = (lane & 16) != 0; \
    const bool h3 = (lane & 8)  != 0; \
    const bool h2 = (lane & 4)  != 0; \
    const bool h1 = (lane & 2)  != 0; \
    const bool two = (!h3) && (!h2); \
    const int  m4 = lane & 15; \
    const int  f  = (m4==0) ? 0 : (m4==2) ? 1 : (m4==4) ? 2 : (m4==8) ? 3 : 4; \
    const int  eidx = (h4 ? 5 : 0) + f; \
    const bool writer = (m4==0 || m4==2 || m4==4 || m4==8 || m4==12);

#define SPLIT_BUTTERFLY(p0,p1,p2,p3,p4,p5,p6,p7,p8,p9,z) \
    { \
    float v0, v1, v2, v3, v4; \
    { \
        float q, t; \
        q = h4 ? p0 : p5; t = __shfl_xor_sync(0xffffffffu, q, 16); v0 = (h4 ? p5 : p0) + t; \
        q = h4 ? p1 : p6; t = __shfl_xor_sync(0xffffffffu, q, 16); v1 = (h4 ? p6 : p1) + t; \
        q = h4 ? p2 : p7; t = __shfl_xor_sync(0xffffffffu, q, 16); v2 = (h4 ? p7 : p2) + t; \
        q = h4 ? p3 : p8; t = __shfl_xor_sync(0xffffffffu, q, 16); v3 = (h4 ? p8 : p3) + t; \
        q = h4 ? p4 : p9; t = __shfl_xor_sync(0xffffffffu, q, 16); v4 = (h4 ? p9 : p4) + t; \
    } \
    float w0, w1, w2; \
    { \
        float q0 = h3 ? v0 : v3; \
        float q1 = h3 ? v1 : v4; \
        float q2 = v2; \
        float t0s = __shfl_xor_sync(0xffffffffu, q0, 8); \
        float t1s = __shfl_xor_sync(0xffffffffu, q1, 8); \
        float t2s = __shfl_xor_sync(0xffffffffu, q2, 8); \
        if (!h3) { w0 = v0 + t0s; w1 = v1 + t1s; w2 = v2 + t2s; } \
        else     { w0 = v3 + t0s; w1 = v4 + t1s; w2 = 0.f; } \
    } \
    float u0, u1; \
    { \
        float q0 = h2 ? w0 : (h3 ? w1 : w2); \
        float q1 = w1; \
        float t0s = __shfl_xor_sync(0xffffffffu, q0, 4); \
        float t1s = __shfl_xor_sync(0xffffffffu, q1, 4); \
        if (!h3) { \
            if (!h2) { u0 = w0 + t0s; u1 = w1 + t1s; } \
            else     { u0 = w2 + t0s; u1 = 0.f; } \
        } else { \
            u0 = (h2 ? w1 : w0) + t0s; u1 = 0.f; \
        } \
    } \
    { \
        float q = two ? (h1 ? u0 : u1) : u0; \
        float t = __shfl_xor_sync(0xffffffffu, q, 2); \
        z = (two ? (h1 ? u1 : u0) : u0) + t; \
    } \
    z += __shfl_xor_sync(0xffffffffu, z, 1); \
    }

// ---- sigma0 body (K=7): float2 channels, warp = whole channel set -----------
template<int R, int SEGH, int NCH>
__device__ __forceinline__ void s2_body0(int bxi, int byi, int b, int tid) {
    constexpr int K = 2*R + 1;
    const int warp = tid >> 5, lane = tid & 31;
    const int x    = bxi*8 + warp;
    const int ys   = byi*SEGH;
    const int rs   = WW*32;
    const size_t base = ((size_t)(b*HH*WW) + x)*32 + lane;
    const float2* X0 = (const float2*)g_X[0] + base;
    const float2* X1 = (const float2*)g_X[1] + base;
    const float2* X2 = (const float2*)g_X[2] + base;

    float4 fe[R+1]; float2 fo[R];
    #pragma unroll
    for (int t = 0; t <= R; ++t) fe[t] = g_fe[0][t];
    #pragma unroll
    for (int t = 0; t <  R; ++t) fo[t] = g_fo[0][t];

    REDUCE_ROUTING();
    float* PbE = &g_P0[(size_t)eidx*BHW + (size_t)b*HH*WW + x];

    const float2 Z2 = make_float2(0.f, 0.f);
    float2 r0[K], r1[K], r2[K];
    #pragma unroll
    for (int j = 0; j < K - 1; ++j) {
        int yy = ys - R + j;
        const int sl = (j + K - R) % K;
        bool ok = (yy >= 0 && yy < HH);
        r0[sl] = ok ? X0[(size_t)yy*rs] : Z2;
        r1[sl] = ok ? X1[(size_t)yy*rs] : Z2;
        r2[sl] = ok ? X2[(size_t)yy*rs] : Z2;
    }
    float2 t0, t1, t2;
    {
        int yy = ys + R;
        bool ok = yy < HH;
        t0 = ok ? X0[(size_t)yy*rs] : Z2;
        t1 = ok ? X1[(size_t)yy*rs] : Z2;
        t2 = ok ? X2[(size_t)yy*rs] : Z2;
    }

    int y = ys;
    for (int ch = 0; ch < NCH; ++ch) {
        #pragma unroll
        for (int i = 0; i < K; ++i, ++y) {
            {
                const int slN = (i + R) % K;
                r0[slN] = t0; r1[slN] = t1; r2[slN] = t2;
            }
            {
                int yy = y + 1 + R;
                bool ok = yy < HH;
                t0 = ok ? X0[(size_t)yy*rs] : Z2;
                t1 = ok ? X1[(size_t)yy*rs] : Z2;
                t2 = ok ? X2[(size_t)yy*rs] : Z2;
            }
            float2 L0=Z2, L1=Z2, L2=Z2, L3=Z2, L4=Z2, L5=Z2;
            #pragma unroll
            for (int j = 0; j < R; ++j) {
                const int sa = (i + j + (K - R)) % K;
                const int sb = (i + (K - 1 - j) + (K - R)) % K;
                float2 a0 = r0[sa], b0 = r0[sb];
                float2 a1 = r1[sa], b1 = r1[sb];
                float2 a2 = r2[sa], b2 = r2[sb];
                float s0x = a0.x + b0.x, s0y = a0.y + b0.y;
                float d0x = a0.x - b0.x, d0y = a0.y - b0.y;
                float s1x = a1.x + b1.x, s1y = a1.y + b1.y;
                float d1x = a1.x - b1.x, d1y = a1.y - b1.y;
                float s2x = a2.x + b2.x, s2y = a2.y + b2.y;
                L0.x = fmaf(fe[j].x, s0x, L0.x); L0.y = fmaf(fe[j].x, s0y, L0.y);
                L3.x = fmaf(fe[j].y, s0x, L3.x); L3.y = fmaf(fe[j].y, s0y, L3.y);
                L2.x = fmaf(fe[j].z, s1x, L2.x); L2.y = fmaf(fe[j].z, s1y, L2.y);
                L5.x = fmaf(fe[j].w, s2x, L5.x); L5.y = fmaf(fe[j].w, s2y, L5.y);
                L1.x = fmaf(fo[j].x, d0x, L1.x); L1.y = fmaf(fo[j].x, d0y, L1.y);
                L4.x = fmaf(fo[j].y, d1x, L4.x); L4.y = fmaf(fo[j].y, d1y, L4.y);
            }
            {
                L0.x = fmaf(fe[R].x, r0[i].x, L0.x); L0.y = fmaf(fe[R].x, r0[i].y, L0.y);
                L3.x = fmaf(fe[R].y, r0[i].x, L3.x); L3.y = fmaf(fe[R].y, r0[i].y, L3.y);
                L2.x = fmaf(fe[R].z, r1[i].x, L2.x); L2.y = fmaf(fe[R].z, r1[i].y, L2.y);
                L5.x = fmaf(fe[R].w, r2[i].x, L5.x); L5.y = fmaf(fe[R].w, r2[i].y, L5.y);
            }
            float p0 = fmaf(L0.y, L0.y, L0.x*L0.x);
            float p1 = fmaf(L1.y, L1.y, L1.x*L1.x);
            float p2 = fmaf(L1.y, L2.y, L1.x*L2.x);
            float p3 = fmaf(L2.y, L2.y, L2.x*L2.x);
            float p4 = fmaf(L3.y, L3.y, L3.x*L3.x);
            float p5 = fmaf(L3.y, L4.y, L3.x*L4.x);
            float p6 = fmaf(L3.y, L5.y, L3.x*L5.x);
            float p7 = fmaf(L4.y, L4.y, L4.x*L4.x);
            float p8 = fmaf(L4.y, L5.y, L4.x*L5.x);
            float p9 = fmaf(L5.y, L5.y, L5.x*L5.x);
            float z;
            SPLIT_BUTTERFLY(p0,p1,p2,p3,p4,p5,p6,p7,p8,p9,z);
            if (writer && y < HH)
                PbE[y*WW] = z;
        }
    }
}

// ---- sigma1 body (K=13): 1 channel/lane, 2 warps per x; 2-pixel interleave --
// Coefficients in SMEM (each LDS amortized over 2 pixels); two independent
// butterflies per pair sit in one basic block for ILP.
template<int R, int SEGH, int NCH>
__device__ __forceinline__ void s2_body1(int bxi, int byi, int b, int tid,
                                         const float4* fe, const float2* fo) {
    constexpr int K = 2*R + 1;
    const int warp = tid >> 5, lane = tid & 31;
    const int xi   = warp >> 1, chalf = warp & 1;
    const int x    = bxi*4 + xi;
    const int ys   = byi*SEGH;
    const int rs   = WW*CC;
    const size_t base = ((size_t)(b*HH*WW) + x)*CC + chalf*32 + lane;
    const float* X0 = g_X[3] + base;
    const float* X1 = g_X[4] + base;
    const float* X2 = g_X[5] + base;

    REDUCE_ROUTING();
    float* PbE = &g_P1[(size_t)(eidx*2 + chalf)*BHW + (size_t)b*HH*WW + x];

    float r0[K], r1[K], r2[K];
    #pragma unroll
    for (int j = 0; j < K - 1; ++j) {
        int yy = ys - R + j;
        const int sl = (j + K - R) % K;
        bool ok = (yy >= 0 && yy < HH);
        r0[sl] = ok ? X0[(size_t)yy*rs] : 0.f;
        r1[sl] = ok ? X1[(size_t)yy*rs] : 0.f;
        r2[sl] = ok ? X2[(size_t)yy*rs] : 0.f;
    }

    int y = ys;
    for (int ch = 0; ch < NCH; ++ch) {
        #pragma unroll
        for (int ii = 0; ii < K; ii += 2) {
            if (ii < K - 1) {
                // ---- pixel pair: A at y (ring idx ii), B at y+1 (ring idx ii+1)
                {
                    int yy = y + R;  bool ok  = yy  < HH;
                    int yz = yy + 1; bool ok2 = yz  < HH;
                    const int sA = (ii + R) % K;
                    const int sB = (ii + 1 + R) % K;
                    r0[sA] = ok ? X0[(size_t)yy*rs] : 0.f;
                    r1[sA] = ok ? X1[(size_t)yy*rs] : 0.f;
                    r2[sA] = ok ? X2[(size_t)yy*rs] : 0.f;
                    r0[sB] = ok2 ? X0[(size_t)yz*rs] : 0.f;
                    r1[sB] = ok2 ? X1[(size_t)yz*rs] : 0.f;
                    r2[sB] = ok2 ? X2[(size_t)yz*rs] : 0.f;
                }
                float A0=0.f,A1=0.f,A2=0.f,A3=0.f,A4=0.f,A5=0.f;
                float C0=0.f,C1=0.f,C2=0.f,C3=0.f,C4=0.f,C5=0.f;
                #pragma unroll
                for (int j = 0; j < R; ++j) {
                    const float4 ce = fe[j];
                    const float2 co = fo[j];
                    {
                        const int sa = (ii + j + (K - R)) % K;
                        const int sb = (ii + (K - 1 - j) + (K - R)) % K;
                        float s0 = r0[sa] + r0[sb], d0 = r0[sa] - r0[sb];
                        float s1 = r1[sa] + r1[sb], d1 = r1[sa] - r1[sb];
                        float s2 = r2[sa] + r2[sb];
                        A0 = fmaf(ce.x, s0, A0);
                        A3 = fmaf(ce.y, s0, A3);
                        A2 = fmaf(ce.z, s1, A2);
                        A5 = fmaf(ce.w, s2, A5);
                        A1 = fmaf(co.x, d0, A1);
                        A4 = fmaf(co.y, d1, A4);
                    }
                    {
                        const int sa = (ii + 1 + j + (K - R)) % K;
                        const int sb = (ii + 1 + (K - 1 - j) + (K - R)) % K;
                        float s0 = r0[sa] + r0[sb], d0 = r0[sa] - r0[sb];
                        float s1 = r1[sa] + r1[sb], d1 = r1[sa] - r1[sb];
                        float s2 = r2[sa] + r2[sb];
                        C0 = fmaf(ce.x, s0, C0);
                        C3 = fmaf(ce.y, s0, C3);
                        C2 = fmaf(ce.z, s1, C2);
                        C5 = fmaf(ce.w, s2, C5);
                        C1 = fmaf(co.x, d0, C1);
                        C4 = fmaf(co.y, d1, C4);
                    }
                }
                {
                    const float4 ce = fe[R];
                    A0 = fmaf(ce.x, r0[ii], A0);
                    A3 = fmaf(ce.y, r0[ii], A3);
                    A2 = fmaf(ce.z, r1[ii], A2);
                    A5 = fmaf(ce.w, r2[ii], A5);
                    C0 = fmaf(ce.x, r0[ii+1], C0);
                    C3 = fmaf(ce.y, r0[ii+1], C3);
                    C2 = fmaf(ce.z, r1[ii+1], C2);
                    C5 = fmaf(ce.w, r2[ii+1], C5);
                }
                float pa0 = A0*A0, pa1 = A1*A1, pa2 = A1*A2, pa3 = A2*A2, pa4 = A3*A3;
                float pa5 = A3*A4, pa6 = A3*A5, pa7 = A4*A4, pa8 = A4*A5, pa9 = A5*A5;
                float pb0 = C0*C0, pb1 = C1*C1, pb2 = C1*C2, pb3 = C2*C2, pb4 = C3*C3;
                float pb5 = C3*C4, pb6 = C3*C5, pb7 = C4*C4, pb8 = C4*C5, pb9 = C5*C5;
                float za, zb;
                SPLIT_BUTTERFLY(pa0,pa1,pa2,pa3,pa4,pa5,pa6,pa7,pa8,pa9,za);
                SPLIT_BUTTERFLY(pb0,pb1,pb2,pb3,pb4,pb5,pb6,pb7,pb8,pb9,zb);
                if (writer && y < HH)     PbE[y*WW] = za;
                if (writer && y + 1 < HH) PbE[(y+1)*WW] = zb;
                y += 2;
            } else {
                // ---- leftover single pixel (ii == K-1)
                {
                    int yy = y + R; bool ok = yy < HH;
                    const int sA = (ii + R) % K;
                    r0[sA] = ok ? X0[(size_t)yy*rs] : 0.f;
                    r1[sA] = ok ? X1[(size_t)yy*rs] : 0.f;
                    r2[sA] = ok ? X2[(size_t)yy*rs] : 0.f;
                }
                float A0=0.f,A1=0.f,A2=0.f,A3=0.f,A4=0.f,A5=0.f;
                #pragma unroll
                for (int j = 0; j < R; ++j) {
                    const float4 ce = fe[j];
                    const float2 co = fo[j];
                    const int sa = (ii + j + (K - R)) % K;
                    const int sb = (ii + (K - 1 - j) + (K - R)) % K;
                    float s0 = r0[sa] + r0[sb], d0 = r0[sa] - r0[sb];
                    float s1 = r1[sa] + r1[sb], d1 = r1[sa] - r1[sb];
                    float s2 = r2[sa] + r2[sb];
                    A0 = fmaf(ce.x, s0, A0);
                    A3 = fmaf(ce.y, s0, A3);
                    A2 = fmaf(ce.z, s1, A2);
                    A5 = fmaf(ce.w, s2, A5);
                    A1 = fmaf(co.x, d0, A1);
                    A4 = fmaf(co.y, d1, A4);
                }
                {
                    const float4 ce = fe[R];
                    A0 = fmaf(ce.x, r0[ii], A0);
                    A3 = fmaf(ce.y, r0[ii], A3);
                    A2 = fmaf(ce.z, r1[ii], A2);
                    A5 = fmaf(ce.w, r2[ii], A5);
                }
                float pa0 = A0*A0, pa1 = A1*A1, pa2 = A1*A2, pa3 = A2*A2, pa4 = A3*A3;
                float pa5 = A3*A4, pa6 = A3*A5, pa7 = A4*A4, pa8 = A4*A5, pa9 = A5*A5;
                float za;
                SPLIT_BUTTERFLY(pa0,pa1,pa2,pa3,pa4,pa5,pa6,pa7,pa8,pa9,za);
                if (writer && y < HH) PbE[y*WW] = za;
                y += 1;
            }
        }
    }
}

// ---- fused stage 2: sigma1 blocks first (longest), sigma0 backfills ---------
#define S1_BLOCKS (48*5*BB)   /* 960 */
#define S0_BLOCKS (24*7*BB)   /* 672 */
__global__ void __launch_bounds__(256, 2) stage2_fused() {
    __shared__ float4 s_fe[7];
    __shared__ float2 s_fo[6];
    const int tid = threadIdx.x;
    int blk = blockIdx.x;
    if (blk < S1_BLOCKS) {
        if (tid < 7) s_fe[tid] = g_fe[1][tid];
        if (tid >= 32 && tid < 38) s_fo[tid - 32] = g_fo[1][tid - 32];
        __syncthreads();
        int bxi = blk % 48, r = blk / 48;
        s2_body1<6, 39, 3>(bxi, r % 5, r / 5, tid, s_fe, s_fo);
    } else {
        blk -= S1_BLOCKS;
        int bxi = blk % 24, r = blk / 24;
        s2_body0<3, 28, 4>(bxi, r % 7, r / 7, tid);
    }
}

// ------- stage 3: separable 7x7 VALID integration + Newton-identity ESPs ----
// All tile index math hoisted out of the per-map loops.
__global__ void __launch_bounds__(256) stage3(float* __restrict__ out) {
    __shared__ float sP[10*484];
    __shared__ float sQ[10*352];
    const int tid = threadIdx.x;
    const int b = blockIdx.z;
    const int y0 = blockIdx.y*16, x0 = blockIdx.x*16;
    const int ty = tid >> 4, tx = tid & 15;
    const int yo = y0 + ty, xo = x0 + tx;
    const bool inb = (yo < HO) && (xo < HO);

    float wy[7], wx[7];
    #pragma unroll
    for (int i = 0; i < 7; ++i) { wy[i] = g_wy[i]; wx[i] = g_wx[i]; }

    // hoisted load coordinates: each thread covers sP entries tid and tid+256
    const int i1 = tid, i2 = tid + 256;
    const int r1 = i1 / 22, c1 = i1 - r1*22;
    const int r2 = i2 / 22, c2 = i2 - r2*22;
    const bool l2ok = (i2 < 484);
    const bool v1g = (y0 + r1 < HH) && (x0 + c1 < WW);
    const bool v2g = l2ok && (y0 + r2 < HH) && (x0 + c2 < WW);
    const size_t pix1 = (size_t)(b*HH + y0 + r1)*WW + (x0 + c1);
    const size_t pix2 = (size_t)(b*HH + y0 + r2)*WW + (x0 + c2);
    // hoisted pass-1 coordinates: sQ entries tid and tid+256 (352 = 22*16)
    const int q2 = tid + 256;
    const bool q2v = (q2 < 352);
    const int qo1 = (tid >> 4)*22 + (tid & 15);
    const int qo2 = (q2  >> 4)*22 + (q2  & 15);

    float M[20];
    #pragma unroll
    for (int chunk = 0; chunk < 2; ++chunk) {
        #pragma unroll
        for (int se = 0; se < 10; ++se) {
            float v1 = 0.f, v2 = 0.f;
            if (chunk == 0) {
                const float* P = &g_P0[(size_t)se*BHW];
                if (v1g) v1 = P[pix1];
                if (v2g) v2 = P[pix2];
            } else {
                const float* Pa = &g_P1[(size_t)(se*2)*BHW];
                const float* Pb = &g_P1[(size_t)(se*2 + 1)*BHW];
                if (v1g) v1 = Pa[pix1] + Pb[pix1];
                if (v2g) v2 = Pa[pix2] + Pb[pix2];
            }
            sP[se*484 + i1] = v1;
            if (l2ok) sP[se*484 + i2] = v2;
        }
        __syncthreads();
        #pragma unroll
        for (int se = 0; se < 10; ++se) {
            {
                const float* row = &sP[se*484 + qo1];
                float a = 0.f;
                #pragma unroll
                for (int j = 0; j < 7; ++j) a = fmaf(wx[j], row[j], a);
                sQ[se*352 + tid] = a;
            }
            if (q2v) {
                const float* row = &sP[se*484 + qo2];
                float a = 0.f;
                #pragma unroll
                for (int j = 0; j < 7; ++j) a = fmaf(wx[j], row[j], a);
                sQ[se*352 + q2] = a;
            }
        }
        __syncthreads();
        #pragma unroll
        for (int s = 0; s < 10; ++s) {
            float a = 0.f;
            const float* col = &sQ[s*352 + ty*16 + tx];
            #pragma unroll
            for (int i = 0; i < 7; ++i) a = fmaf(wy[i], col[i*16], a);
            M[chunk*10 + s] = a;
        }
        __syncthreads();
    }
    if (!inb) return;

    const float EPSF = 2.2204460492503131e-16f;
    float res[12];
    #pragma unroll
    for (int s = 0; s < 2; ++s) {
        const float* Ms = M + s*10;
        res[s*6 + 0] = fabsf(Ms[0]) + EPSF;
        {
            float a = Ms[1], bq = Ms[2], c2v = Ms[3];
            float p1 = a + c2v;
            float p2 = a*a + 2.f*bq*bq + c2v*c2v;
            float e1 = p1;
            float e2 = 0.5f*(p1*e1 - p2);
            res[s*6 + 1] = 10.f*(fabsf(e1) + EPSF);
            res[s*6 + 2] = 10.f*sqrtf(fabsf(e2) + EPSF);
        }
        {
            float a = Ms[4], bq = Ms[5], cq = Ms[6], d = Ms[7], e = Ms[8], f = Ms[9];
            float p1 = a + d + f;
            float p2 = a*a + d*d + f*f + 2.f*(bq*bq + cq*cq + e*e);
            float p3 = a*a*a + d*d*d + f*f*f
                     + 3.f*(a*(bq*bq + cq*cq) + d*(bq*bq + e*e) + f*(cq*cq + e*e))
                     + 6.f*bq*cq*e;
            float e1 = p1;
            float e2 = 0.5f*(p1*e1 - p2);
            float e3 = (p1*e2 - p2*e1 + p3)*(1.f/3.f);
            res[s*6 + 3] = 100.f*(fabsf(e1) + EPSF);
            res[s*6 + 4] = 100.f*sqrtf(fabsf(e2) + EPSF);
            res[s*6 + 5] = 100.f*cbrtf(fabsf(e3) + EPSF);
        }
    }
    float* op = out + ((size_t)(b*HO + yo)*HO + xo)*12;
    #pragma unroll
    for (int chn = 0; chn < 12; ++chn) op[chn] = res[chn];
}

// ---------------- launcher ---------------------------------------------------
extern "C" void kernel_launch(void* const* d_in, const int* in_sizes, int n_in,
                              void* d_out, int out_size) {
    const float* in  = (const float*)d_in[0];
    const float* k0  = (const float*)d_in[1];
    const float* k1  = (const float*)d_in[2];
    const float* dgi = (const float*)d_in[3];
    float* out = (float*)d_out;

    factorize<<<1, 256>>>(k0, k1, dgi);
    stage1_both<<<dim3(3, HH, BB), 256>>>(in);
    stage2_fused<<<S1_BLOCKS + S0_BLOCKS, 256>>>();
    stage3<<<dim3(12, 12, BB), 256>>>(out);
}

// round 16
// speedup vs baseline: 1.1831x; 1.0238x over previous
#include <cuda_runtime.h>
#include <math.h>

#define BB 4
#define HH 192
#define WW 192
#define CC 64
#define HO 186
#define BHW (BB*HH*WW)          /* 147456 */
#define NELEM (BB*HH*WW*CC)     /* 9437184 */

// ---------------- scratch (device globals; no allocs allowed) ----------------
__device__ __align__(256) float g_X[6][NELEM]; // x-conv: [sigma*3+order]
__device__ float  g_P0[10*BHW];    // sigma0: [e][b*H*W] full channel sums
__device__ float  g_P1[10*2*BHW];  // sigma1: [e*2+chalf][b*H*W] half sums
__device__ float2 g_fxe[2][7];     // x-factors folded: (ord0, ord2) taps 0..R
__device__ float  g_fxo[2][6];     // x-factor order1 taps 0..R-1 (antisym)
__device__ float4 g_fe[2][7];      // y-factors even maps: (L0, L3, L2, L5)
__device__ float2 g_fo[2][6];      // y-factors odd  maps: (L1, L4)
__device__ float  g_wy[7];         // integrator y factor
__device__ float  g_wx[7];         // integrator x factor

// -------- factorization: parallel load to smem, warp argmax, tiny serial tail
__global__ void __launch_bounds__(256) factorize(const float* __restrict__ k0,
                                                 const float* __restrict__ k1,
                                                 const float* __restrict__ dgi) {
    __shared__ float sk[294 + 1014 + 49];
    __shared__ int   s_r0[7], s_c0[7];
    __shared__ float s_piv[7];
    float* sk0 = sk;
    float* sk1 = sk + 294;
    float* sdg = sk + 294 + 1014;
    const int tid = threadIdx.x;
    for (int i = tid; i < 294;  i += 256) sk0[i] = k0[(size_t)i*CC];
    for (int i = tid; i < 1014; i += 256) sk1[i] = k1[(size_t)i*CC];
    for (int i = tid; i < 49;   i += 256) sdg[i] = dgi[(size_t)i*CC];
    __syncthreads();

    const int warp = tid >> 5, lane = tid & 31;
    const int canon[3] = {0, 2, 5};
    if (warp < 7) {
        const float* base; int Ksz, n;
        if (warp < 3)      { base = sk0 + canon[warp]*49;        Ksz = 7;  n = 49;  }
        else if (warp < 6) { base = sk1 + canon[warp - 3]*169;   Ksz = 13; n = 169; }
        else               { base = sdg;                          Ksz = 7;  n = 49;  }
        float best = -1.f; int bidx = 0;
        for (int i = lane; i < n; i += 32) {
            float v = fabsf(base[i]);
            if (v > best) { best = v; bidx = i; }
        }
        #pragma unroll
        for (int off = 16; off >= 1; off >>= 1) {
            float ob = __shfl_xor_sync(0xffffffffu, best, off);
            int   oi = __shfl_xor_sync(0xffffffffu, bidx, off);
            if (ob > best || (ob == best && oi < bidx)) { best = ob; bidx = oi; }
        }
        if (lane == 0) {
            s_r0[warp] = bidx / Ksz; s_c0[warp] = bidx % Ksz; s_piv[warp] = base[bidx];
        }
    }
    __syncthreads();

    if (tid != 0) return;
    const int kxo[6]  = {0, 0, 1, 0, 1, 2};
    const float comb[6] = {1.f, 1.f, 1.f, 1.f, 1.41421356237309515f, 1.f};
    for (int s = 0; s < 2; ++s) {
        const float* skb = s ? sk1 : sk0;
        const int Ksz = s ? 13 : 7, R = (Ksz - 1)/2, per = Ksz*Ksz;
        float fx[3][13]; int c0s[3];
        for (int o = 0; o < 3; ++o) {
            const int task = s*3 + o;
            const int r0 = s_r0[task]; c0s[o] = s_c0[task];
            const float piv = s_piv[task];
            const float* Km = skb + canon[o]*per;
            for (int j = 0; j < Ksz; ++j) fx[o][j] = Km[r0*Ksz + j] / piv;
        }
        for (int t = 0; t <= R; ++t) g_fxe[s][t] = make_float2(fx[0][t], fx[2][t]);
        for (int t = 0; t <  R; ++t) g_fxo[s][t] = fx[1][t];
        float fy[6][13];
        for (int m = 0; m < 6; ++m) {
            const int c0 = c0s[kxo[m]];
            for (int i = 0; i < Ksz; ++i) fy[m][i] = skb[m*per + i*Ksz + c0] * comb[m];
        }
        for (int t = 0; t <= R; ++t)
            g_fe[s][t] = make_float4(fy[0][t], fy[3][t], fy[2][t], fy[5][t]);
        for (int t = 0; t <  R; ++t)
            g_fo[s][t] = make_float2(fy[1][t], fy[4][t]);
    }
    {
        const int r0 = s_r0[6], c0 = s_c0[6]; const float piv = s_piv[6];
        for (int i = 0; i < 7; ++i) g_wy[i] = sdg[i*7 + c0];
        for (int j = 0; j < 7; ++j) g_wx[j] = sdg[r0*7 + j] / piv;
    }
}

// ------- stage 1 (merged): x-convs for BOTH sigmas, orders 0..2 each --------
__global__ void __launch_bounds__(256) stage1_both(const float* __restrict__ in) {
    constexpr int XT = 64;
    __shared__ float2 s_in[(XT + 12)*32];
    const int b = blockIdx.z, yrow = blockIdx.y, x0 = blockIdx.x*XT;
    const int tid = threadIdx.x;
    const float2* rowv = (const float2*)(in + ((size_t)(b*HH + yrow)*WW)*CC);
    for (int t = tid; t < (XT + 12)*32; t += 256) {
        int xx = (t >> 5) - 6 + x0;
        int c2 = t & 31;
        s_in[t] = (xx >= 0 && xx < WW) ? rowv[xx*32 + c2] : make_float2(0.f, 0.f);
    }
    float2 fxe0[4], fxe1[7]; float fxo0[3], fxo1[6];
    #pragma unroll
    for (int t = 0; t < 4; ++t) fxe0[t] = g_fxe[0][t];
    #pragma unroll
    for (int t = 0; t < 3; ++t) fxo0[t] = g_fxo[0][t];
    #pragma unroll
    for (int t = 0; t < 7; ++t) fxe1[t] = g_fxe[1][t];
    #pragma unroll
    for (int t = 0; t < 6; ++t) fxo1[t] = g_fxo[1][t];
    __syncthreads();

    const int c2 = tid & 31, xg = tid >> 5;
    const size_t obase = ((size_t)(b*HH + yrow)*WW)*CC;
    float2* o00 = (float2*)&g_X[0][obase];
    float2* o01 = (float2*)&g_X[1][obase];
    float2* o02 = (float2*)&g_X[2][obase];
    float2* o10 = (float2*)&g_X[3][obase];
    float2* o11 = (float2*)&g_X[4][obase];
    float2* o12 = (float2*)&g_X[5][obase];
    #pragma unroll
    for (int xq = 0; xq < 8; ++xq) {
        int xi = xg*8 + xq;
        float2 A0={0.f,0.f}, A1={0.f,0.f}, A2={0.f,0.f};
        float2 B0={0.f,0.f}, B1={0.f,0.f}, B2={0.f,0.f};
        #pragma unroll
        for (int t = 0; t < 6; ++t) {
            float2 u = s_in[(xi + t)*32 + c2];
            float2 v = s_in[(xi + 12 - t)*32 + c2];
            float sx = u.x + v.x, sy = u.y + v.y;
            float dx = u.x - v.x, dy = u.y - v.y;
            B0.x = fmaf(fxe1[t].x, sx, B0.x); B0.y = fmaf(fxe1[t].x, sy, B0.y);
            B2.x = fmaf(fxe1[t].y, sx, B2.x); B2.y = fmaf(fxe1[t].y, sy, B2.y);
            B1.x = fmaf(fxo1[t],   dx, B1.x); B1.y = fmaf(fxo1[t],   dy, B1.y);
            if (t >= 3) {
                const int t0 = t - 3;
                A0.x = fmaf(fxe0[t0].x, sx, A0.x); A0.y = fmaf(fxe0[t0].x, sy, A0.y);
                A2.x = fmaf(fxe0[t0].y, sx, A2.x); A2.y = fmaf(fxe0[t0].y, sy, A2.y);
                A1.x = fmaf(fxo0[t0],   dx, A1.x); A1.y = fmaf(fxo0[t0],   dy, A1.y);
            }
        }
        float2 m = s_in[(xi + 6)*32 + c2];
        B0.x = fmaf(fxe1[6].x, m.x, B0.x); B0.y = fmaf(fxe1[6].x, m.y, B0.y);
        B2.x = fmaf(fxe1[6].y, m.x, B2.x); B2.y = fmaf(fxe1[6].y, m.y, B2.y);
        A0.x = fmaf(fxe0[3].x, m.x, A0.x); A0.y = fmaf(fxe0[3].x, m.y, A0.y);
        A2.x = fmaf(fxe0[3].y, m.x, A2.x); A2.y = fmaf(fxe0[3].y, m.y, A2.y);
        int off = (x0 + xi)*32 + c2;
        o00[off] = A0; o01[off] = A1; o02[off] = A2;
        o10[off] = B0; o11[off] = B1; o12[off] = B2;
    }
}

// ---- reduction routing shared by both stage2 bodies -------------------------
#define REDUCE_ROUTING() \
    const bool h4 = (lane & 16) != 0; \
    const bool h3 = (lane & 8)  != 0; \
    const bool h2 = (lane & 4)  != 0; \
    const bool h1 = (lane & 2)  != 0; \
    const bool two = (!h3) && (!h2); \
    const int  m4 = lane & 15; \
    const int  f  = (m4==0) ? 0 : (m4==2) ? 1 : (m4==4) ? 2 : (m4==8) ? 3 : 4; \
    const int  eidx = (h4 ? 5 : 0) + f; \
    const bool writer = (m4==0 || m4==2 || m4==4 || m4==8 || m4==12);

#define SPLIT_BUTTERFLY(p0,p1,p2,p3,p4,p5,p6,p7,p8,p9,z) \
    { \
    float v0, v1, v2, v3, v4; \
    { \
        float q, t; \
        q = h4 ? p0 : p5; t = __shfl_xor_sync(0xffffffffu, q, 16); v0 = (h4 ? p5 : p0) + t; \
        q = h4 ? p1 : p6; t = __shfl_xor_sync(0xffffffffu, q, 16); v1 = (h4 ? p6 : p1) + t; \
        q = h4 ? p2 : p7; t = __shfl_xor_sync(0xffffffffu, q, 16); v2 = (h4 ? p7 : p2) + t; \
        q = h4 ? p3 : p8; t = __shfl_xor_sync(0xffffffffu, q, 16); v3 = (h4 ? p8 : p3) + t; \
        q = h4 ? p4 : p9; t = __shfl_xor_sync(0xffffffffu, q, 16); v4 = (h4 ? p9 : p4) + t; \
    } \
    float w0, w1, w2; \
    { \
        float q0 = h3 ? v0 : v3; \
        float q1 = h3 ? v1 : v4; \
        float q2 = v2; \
        float t0s = __shfl_xor_sync(0xffffffffu, q0, 8); \
        float t1s = __shfl_xor_sync(0xffffffffu, q1, 8); \
        float t2s = __shfl_xor_sync(0xffffffffu, q2, 8); \
        if (!h3) { w0 = v0 + t0s; w1 = v1 + t1s; w2 = v2 + t2s; } \
        else     { w0 = v3 + t0s; w1 = v4 + t1s; w2 = 0.f; } \
    } \
    float u0, u1; \
    { \
        float q0 = h2 ? w0 : (h3 ? w1 : w2); \
        float q1 = w1; \
        float t0s = __shfl_xor_sync(0xffffffffu, q0, 4); \
        float t1s = __shfl_xor_sync(0xffffffffu, q1, 4); \
        if (!h3) { \
            if (!h2) { u0 = w0 + t0s; u1 = w1 + t1s; } \
            else     { u0 = w2 + t0s; u1 = 0.f; } \
        } else { \
            u0 = (h2 ? w1 : w0) + t0s; u1 = 0.f; \
        } \
    } \
    { \
        float q = two ? (h1 ? u0 : u1) : u0; \
        float t = __shfl_xor_sync(0xffffffffu, q, 2); \
        z = (two ? (h1 ? u1 : u0) : u0) + t; \
    } \
    z += __shfl_xor_sync(0xffffffffu, z, 1); \
    }

// ---- sigma0 body (K=7): float2 channels, warp = whole channel set -----------
template<int R, int SEGH, int NCH>
__device__ __forceinline__ void s2_body0(int bxi, int byi, int b, int tid) {
    constexpr int K = 2*R + 1;
    const int warp = tid >> 5, lane = tid & 31;
    const int x    = bxi*8 + warp;
    const int ys   = byi*SEGH;
    const int rs   = WW*32;
    const size_t base = ((size_t)(b*HH*WW) + x)*32 + lane;
    const float2* X0 = (const float2*)g_X[0] + base;
    const float2* X1 = (const float2*)g_X[1] + base;
    const float2* X2 = (const float2*)g_X[2] + base;

    float4 fe[R+1]; float2 fo[R];
    #pragma unroll
    for (int t = 0; t <= R; ++t) fe[t] = g_fe[0][t];
    #pragma unroll
    for (int t = 0; t <  R; ++t) fo[t] = g_fo[0][t];

    REDUCE_ROUTING();
    float* PbE = &g_P0[(size_t)eidx*BHW + (size_t)b*HH*WW + x];

    const float2 Z2 = make_float2(0.f, 0.f);
    float2 r0[K], r1[K], r2[K];
    #pragma unroll
    for (int j = 0; j < K - 1; ++j) {
        int yy = ys - R + j;
        const int sl = (j + K - R) % K;
        bool ok = (yy >= 0 && yy < HH);
        r0[sl] = ok ? X0[(size_t)yy*rs] : Z2;
        r1[sl] = ok ? X1[(size_t)yy*rs] : Z2;
        r2[sl] = ok ? X2[(size_t)yy*rs] : Z2;
    }
    float2 t0, t1, t2;
    {
        int yy = ys + R;
        bool ok = yy < HH;
        t0 = ok ? X0[(size_t)yy*rs] : Z2;
        t1 = ok ? X1[(size_t)yy*rs] : Z2;
        t2 = ok ? X2[(size_t)yy*rs] : Z2;
    }

    int y = ys;
    for (int ch = 0; ch < NCH; ++ch) {
        #pragma unroll
        for (int i = 0; i < K; ++i, ++y) {
            {
                const int slN = (i + R) % K;
                r0[slN] = t0; r1[slN] = t1; r2[slN] = t2;
            }
            {
                int yy = y + 1 + R;
                bool ok = yy < HH;
                t0 = ok ? X0[(size_t)yy*rs] : Z2;
                t1 = ok ? X1[(size_t)yy*rs] : Z2;
                t2 = ok ? X2[(size_t)yy*rs] : Z2;
            }
            float2 L0=Z2, L1=Z2, L2=Z2, L3=Z2, L4=Z2, L5=Z2;
            #pragma unroll
            for (int j = 0; j < R; ++j) {
                const int sa = (i + j + (K - R)) % K;
                const int sb = (i + (K - 1 - j) + (K - R)) % K;
                float2 a0 = r0[sa], b0 = r0[sb];
                float2 a1 = r1[sa], b1 = r1[sb];
                float2 a2 = r2[sa], b2 = r2[sb];
                float s0x = a0.x + b0.x, s0y = a0.y + b0.y;
                float d0x = a0.x - b0.x, d0y = a0.y - b0.y;
                float s1x = a1.x + b1.x, s1y = a1.y + b1.y;
                float d1x = a1.x - b1.x, d1y = a1.y - b1.y;
                float s2x = a2.x + b2.x, s2y = a2.y + b2.y;
                L0.x = fmaf(fe[j].x, s0x, L0.x); L0.y = fmaf(fe[j].x, s0y, L0.y);
                L3.x = fmaf(fe[j].y, s0x, L3.x); L3.y = fmaf(fe[j].y, s0y, L3.y);
                L2.x = fmaf(fe[j].z, s1x, L2.x); L2.y = fmaf(fe[j].z, s1y, L2.y);
                L5.x = fmaf(fe[j].w, s2x, L5.x); L5.y = fmaf(fe[j].w, s2y, L5.y);
                L1.x = fmaf(fo[j].x, d0x, L1.x); L1.y = fmaf(fo[j].x, d0y, L1.y);
                L4.x = fmaf(fo[j].y, d1x, L4.x); L4.y = fmaf(fo[j].y, d1y, L4.y);
            }
            {
                L0.x = fmaf(fe[R].x, r0[i].x, L0.x); L0.y = fmaf(fe[R].x, r0[i].y, L0.y);
                L3.x = fmaf(fe[R].y, r0[i].x, L3.x); L3.y = fmaf(fe[R].y, r0[i].y, L3.y);
                L2.x = fmaf(fe[R].z, r1[i].x, L2.x); L2.y = fmaf(fe[R].z, r1[i].y, L2.y);
                L5.x = fmaf(fe[R].w, r2[i].x, L5.x); L5.y = fmaf(fe[R].w, r2[i].y, L5.y);
            }
            float p0 = fmaf(L0.y, L0.y, L0.x*L0.x);
            float p1 = fmaf(L1.y, L1.y, L1.x*L1.x);
            float p2 = fmaf(L1.y, L2.y, L1.x*L2.x);
            float p3 = fmaf(L2.y, L2.y, L2.x*L2.x);
            float p4 = fmaf(L3.y, L3.y, L3.x*L3.x);
            float p5 = fmaf(L3.y, L4.y, L3.x*L4.x);
            float p6 = fmaf(L3.y, L5.y, L3.x*L5.x);
            float p7 = fmaf(L4.y, L4.y, L4.x*L4.x);
            float p8 = fmaf(L4.y, L5.y, L4.x*L5.x);
            float p9 = fmaf(L5.y, L5.y, L5.x*L5.x);
            float z;
            SPLIT_BUTTERFLY(p0,p1,p2,p3,p4,p5,p6,p7,p8,p9,z);
            if (writer && y < HH)
                PbE[y*WW] = z;
        }
    }
}

// ---- sigma1 body (K=13): 1 channel/lane, 2 warps per x (chalf split) --------
template<int R, int SEGH, int NCH>
__device__ __forceinline__ void s2_body1(int bxi, int byi, int b, int tid) {
    constexpr int K = 2*R + 1;
    const int warp = tid >> 5, lane = tid & 31;
    const int xi   = warp >> 1, chalf = warp & 1;
    const int x    = bxi*4 + xi;
    const int ys   = byi*SEGH;
    const int rs   = WW*CC;
    const size_t base = ((size_t)(b*HH*WW) + x)*CC + chalf*32 + lane;
    const float* X0 = g_X[3] + base;
    const float* X1 = g_X[4] + base;
    const float* X2 = g_X[5] + base;

    float4 fe[R+1]; float2 fo[R];
    #pragma unroll
    for (int t = 0; t <= R; ++t) fe[t] = g_fe[1][t];
    #pragma unroll
    for (int t = 0; t <  R; ++t) fo[t] = g_fo[1][t];

    REDUCE_ROUTING();
    float* PbE = &g_P1[(size_t)(eidx*2 + chalf)*BHW + (size_t)b*HH*WW + x];

    float r0[K], r1[K], r2[K];
    #pragma unroll
    for (int j = 0; j < K - 1; ++j) {
        int yy = ys - R + j;
        const int sl = (j + K - R) % K;
        bool ok = (yy >= 0 && yy < HH);
        r0[sl] = ok ? X0[(size_t)yy*rs] : 0.f;
        r1[sl] = ok ? X1[(size_t)yy*rs] : 0.f;
        r2[sl] = ok ? X2[(size_t)yy*rs] : 0.f;
    }
    float t0, t1, t2;
    {
        int yy = ys + R;
        bool ok = yy < HH;
        t0 = ok ? X0[(size_t)yy*rs] : 0.f;
        t1 = ok ? X1[(size_t)yy*rs] : 0.f;
        t2 = ok ? X2[(size_t)yy*rs] : 0.f;
    }

    int y = ys;
    for (int ch = 0; ch < NCH; ++ch) {
        #pragma unroll
        for (int i = 0; i < K; ++i, ++y) {
            {
                const int slN = (i + R) % K;
                r0[slN] = t0; r1[slN] = t1; r2[slN] = t2;
            }
            {
                int yy = y + 1 + R;
                bool ok = yy < HH;
                t0 = ok ? X0[(size_t)yy*rs] : 0.f;
                t1 = ok ? X1[(size_t)yy*rs] : 0.f;
                t2 = ok ? X2[(size_t)yy*rs] : 0.f;
            }
            float L0=0.f, L1=0.f, L2=0.f, L3=0.f, L4=0.f, L5=0.f;
            #pragma unroll
            for (int j = 0; j < R; ++j) {
                const int sa = (i + j + (K - R)) % K;
                const int sb = (i + (K - 1 - j) + (K - R)) % K;
                float s0 = r0[sa] + r0[sb], d0 = r0[sa] - r0[sb];
                float s1 = r1[sa] + r1[sb], d1 = r1[sa] - r1[sb];
                float s2 = r2[sa] + r2[sb];
                L0 = fmaf(fe[j].x, s0, L0);
                L3 = fmaf(fe[j].y, s0, L3);
                L2 = fmaf(fe[j].z, s1, L2);
                L5 = fmaf(fe[j].w, s2, L5);
                L1 = fmaf(fo[j].x, d0, L1);
                L4 = fmaf(fo[j].y, d1, L4);
            }
            {
                L0 = fmaf(fe[R].x, r0[i], L0);
                L3 = fmaf(fe[R].y, r0[i], L3);
                L2 = fmaf(fe[R].z, r1[i], L2);
                L5 = fmaf(fe[R].w, r2[i], L5);
            }
            float p0 = L0*L0, p1 = L1*L1, p2 = L1*L2, p3 = L2*L2, p4 = L3*L3;
            float p5 = L3*L4, p6 = L3*L5, p7 = L4*L4, p8 = L4*L5, p9 = L5*L5;
            float z;
            SPLIT_BUTTERFLY(p0,p1,p2,p3,p4,p5,p6,p7,p8,p9,z);
            if (writer && y < HH)
                PbE[y*WW] = z;
        }
    }
}

// ---- fused stage 2: sigma1 blocks first (longest), sigma0 backfills ---------
#define S1_BLOCKS (48*5*BB)   /* 960 */
#define S0_BLOCKS (24*7*BB)   /* 672 */
__global__ void __launch_bounds__(256, 2) stage2_fused() {
    const int tid = threadIdx.x;
    int blk = blockIdx.x;
    if (blk < S1_BLOCKS) {
        int bxi = blk % 48, r = blk / 48;
        s2_body1<6, 39, 3>(bxi, r % 5, r / 5, tid);
    } else {
        blk -= S1_BLOCKS;
        int bxi = blk % 24, r = blk / 24;
        s2_body0<3, 28, 4>(bxi, r % 7, r / 7, tid);
    }
}

// ------- stage 3: separable 7x7 VALID integration + Newton-identity ESPs ----
// All tile index math hoisted out of the per-map loops.
__global__ void __launch_bounds__(256) stage3(float* __restrict__ out) {
    __shared__ float sP[10*484];
    __shared__ float sQ[10*352];
    const int tid = threadIdx.x;
    const int b = blockIdx.z;
    const int y0 = blockIdx.y*16, x0 = blockIdx.x*16;
    const int ty = tid >> 4, tx = tid & 15;
    const int yo = y0 + ty, xo = x0 + tx;
    const bool inb = (yo < HO) && (xo < HO);

    float wy[7], wx[7];
    #pragma unroll
    for (int i = 0; i < 7; ++i) { wy[i] = g_wy[i]; wx[i] = g_wx[i]; }

    // hoisted load coordinates: each thread covers sP entries tid and tid+256
    const int i1 = tid, i2 = tid + 256;
    const int r1 = i1 / 22, c1 = i1 - r1*22;
    const int r2 = i2 / 22, c2 = i2 - r2*22;
    const bool l2ok = (i2 < 484);
    const bool v1g = (y0 + r1 < HH) && (x0 + c1 < WW);
    const bool v2g = l2ok && (y0 + r2 < HH) && (x0 + c2 < WW);
    const size_t pix1 = (size_t)(b*HH + y0 + r1)*WW + (x0 + c1);
    const size_t pix2 = (size_t)(b*HH + y0 + r2)*WW + (x0 + c2);
    // hoisted pass-1 coordinates: sQ entries tid and tid+256 (352 = 22*16)
    const int q2 = tid + 256;
    const bool q2v = (q2 < 352);
    const int qo1 = (tid >> 4)*22 + (tid & 15);
    const int qo2 = (q2  >> 4)*22 + (q2  & 15);

    float M[20];
    #pragma unroll
    for (int chunk = 0; chunk < 2; ++chunk) {
        #pragma unroll
        for (int se = 0; se < 10; ++se) {
            float v1 = 0.f, v2 = 0.f;
            if (chunk == 0) {
                const float* P = &g_P0[(size_t)se*BHW];
                if (v1g) v1 = P[pix1];
                if (v2g) v2 = P[pix2];
            } else {
                const float* Pa = &g_P1[(size_t)(se*2)*BHW];
                const float* Pb = &g_P1[(size_t)(se*2 + 1)*BHW];
                if (v1g) v1 = Pa[pix1] + Pb[pix1];
                if (v2g) v2 = Pa[pix2] + Pb[pix2];
            }
            sP[se*484 + i1] = v1;
            if (l2ok) sP[se*484 + i2] = v2;
        }
        __syncthreads();
        #pragma unroll
        for (int se = 0; se < 10; ++se) {
            {
                const float* row = &sP[se*484 + qo1];
                float a = 0.f;
                #pragma unroll
                for (int j = 0; j < 7; ++j) a = fmaf(wx[j], row[j], a);
                sQ[se*352 + tid] = a;
            }
            if (q2v) {
                const float* row = &sP[se*484 + qo2];
                float a = 0.f;
                #pragma unroll
                for (int j = 0; j < 7; ++j) a = fmaf(wx[j], row[j], a);
                sQ[se*352 + q2] = a;
            }
        }
        __syncthreads();
        #pragma unroll
        for (int s = 0; s < 10; ++s) {
            float a = 0.f;
            const float* col = &sQ[s*352 + ty*16 + tx];
            #pragma unroll
            for (int i = 0; i < 7; ++i) a = fmaf(wy[i], col[i*16], a);
            M[chunk*10 + s] = a;
        }
        __syncthreads();
    }
    if (!inb) return;

    const float EPSF = 2.2204460492503131e-16f;
    float res[12];
    #pragma unroll
    for (int s = 0; s < 2; ++s) {
        const float* Ms = M + s*10;
        res[s*6 + 0] = fabsf(Ms[0]) + EPSF;
        {
            float a = Ms[1], bq = Ms[2], c2v = Ms[3];
            float p1 = a + c2v;
            float p2 = a*a + 2.f*bq*bq + c2v*c2v;
            float e1 = p1;
            float e2 = 0.5f*(p1*e1 - p2);
            res[s*6 + 1] = 10.f*(fabsf(e1) + EPSF);
            res[s*6 + 2] = 10.f*sqrtf(fabsf(e2) + EPSF);
        }
        {
            float a = Ms[4], bq = Ms[5], cq = Ms[6], d = Ms[7], e = Ms[8], f = Ms[9];
            float p1 = a + d + f;
            float p2 = a*a + d*d + f*f + 2.f*(bq*bq + cq*cq + e*e);
            float p3 = a*a*a + d*d*d + f*f*f
                     + 3.f*(a*(bq*bq + cq*cq) + d*(bq*bq + e*e) + f*(cq*cq + e*e))
                     + 6.f*bq*cq*e;
            float e1 = p1;
            float e2 = 0.5f*(p1*e1 - p2);
            float e3 = (p1*e2 - p2*e1 + p3)*(1.f/3.f);
            res[s*6 + 3] = 100.f*(fabsf(e1) + EPSF);
            res[s*6 + 4] = 100.f*sqrtf(fabsf(e2) + EPSF);
            res[s*6 + 5] = 100.f*cbrtf(fabsf(e3) + EPSF);
        }
    }
    float* op = out + ((size_t)(b*HO + yo)*HO + xo)*12;
    #pragma unroll
    for (int chn = 0; chn < 12; ++chn) op[chn] = res[chn];
}

// ---------------- launcher ---------------------------------------------------
extern "C" void kernel_launch(void* const* d_in, const int* in_sizes, int n_in,
                              void* d_out, int out_size) {
    const float* in  = (const float*)d_in[0];
    const float* k0  = (const float*)d_in[1];
    const float* k1  = (const float*)d_in[2];
    const float* dgi = (const float*)d_in[3];
    float* out = (float*)d_out;

    factorize<<<1, 256>>>(k0, k1, dgi);
    stage1_both<<<dim3(3, HH, BB), 256>>>(in);
    stage2_fused<<<S1_BLOCKS + S0_BLOCKS, 256>>>();
    stage3<<<dim3(12, 12, BB), 256>>>(out);
}